// round 5
// baseline (speedup 1.0000x reference)
#include <cuda_runtime.h>
#include <cuda_fp16.h>
#include <cstdint>
#include <math.h>

#define BB   16
#define CC   256
#define HWN  4096
#define KK   4
#define HIDN 512
#define EPS_W 1e-8f
#define LN_EPS 1e-5f
#define SCALE 0.0625f   // C^-0.5 = 1/16

// ---------------- scratch (static device globals; no allocation) ----------------
static __device__ __align__(16) __half g_xnl [BB*HWN*CC];  // LN'd input, (b,n,c), fp16
static __device__ __align__(16) float g_slots[BB*KK*CC];
static __device__ __align__(16) float g_qt  [BB*KK*CC];    // scale * Wk^T q
static __device__            float g_qb  [BB*KK];          // scale * q.bk
static __device__ __align__(16) float g_A   [BB*KK*CC];
static __device__            float g_S   [BB*KK];
static __device__ __align__(16) float g_spre[BB*KK*CC];
static __device__ __align__(16) float g_h   [BB*KK*HIDN];
static __device__ __align__(16) float g_Wvu [CC*CC];       // Wu2 @ Wv
static __device__            float g_bvu [CC];             // Wu2 @ bv
static __device__ __align__(16) float g_Wqk [CC*CC];       // scale * Wk^T Wq
static __device__            float g_qtb [CC];             // scale * Wk^T bq
static __device__ __align__(16) float g_wqbk[CC];          // scale * Wq^T bk
static __device__            float g_bqbk;                 // scale * bq.bk

// dynamic smem layout for k_attn (bytes)
#define SX_WORDS   (128 * 133)
#define OFF_SX     0
#define OFF_QT     (SX_WORDS * 4)                 // 68096
#define OFF_PART   (OFF_QT + 4 * 128 * 8)         // +4096 = 72192
#define OFF_SA     (OFF_PART + 256 * 16)          // +4096 = 76288
#define OFF_QB     (OFF_SA + 128 * 16)            // +2048 = 78336
#define OFF_SRED   (OFF_QB + 16)                  // 78352
#define SMEM_ATTN  (OFF_SRED + 16 * 4 + 16)       // ~78432

__device__ __forceinline__ float gelu_f(float x) {
    return 0.5f * x * (1.0f + erff(x * 0.70710678118654752f));
}

__device__ __forceinline__ float block_reduce_256(float v, float* red, int tid) {
    red[tid] = v; __syncthreads();
    #pragma unroll
    for (int s = 128; s > 0; s >>= 1) {
        if (tid < s) red[tid] += red[tid + s];
        __syncthreads();
    }
    float r = red[0]; __syncthreads();
    return r;
}

// ---------------- K0a: precompute Wvu = Wu2 @ Wv, bvu = Wu2 @ bv ----------
__global__ void __launch_bounds__(256) k_prep(const float* __restrict__ Wu,
                                              const float* __restrict__ Wv,
                                              const float* __restrict__ bv) {
    __shared__ __align__(16) float sWv[32 * 260];
    __shared__ __align__(16) float wu2s[CC * 4];
    int d0 = blockIdx.x * 4;
    int tid = threadIdx.x;

    for (int idx = tid; idx < CC * 4; idx += 256) {
        int dl = idx & 3, e = idx >> 2;
        wu2s[idx] = Wu[(size_t)(d0 + dl) * 512 + 256 + e];
    }
    __syncthreads();

    float a0 = 0.f, a1 = 0.f, a2 = 0.f, a3 = 0.f;
    for (int ch = 0; ch < 8; ch++) {
        #pragma unroll
        for (int it = 0; it < 32; it++)
            sWv[it * 260 + tid] = Wv[(size_t)(ch * 32 + it) * CC + tid];
        __syncthreads();
        #pragma unroll
        for (int el = 0; el < 32; el++) {
            float x = sWv[el * 260 + tid];
            float4 w = *(const float4*)&wu2s[(ch * 32 + el) * 4];
            a0 += w.x * x; a1 += w.y * x; a2 += w.z * x; a3 += w.w * x;
        }
        __syncthreads();
    }
    g_Wvu[(size_t)(d0 + 0) * CC + tid] = a0;
    g_Wvu[(size_t)(d0 + 1) * CC + tid] = a1;
    g_Wvu[(size_t)(d0 + 2) * CC + tid] = a2;
    g_Wvu[(size_t)(d0 + 3) * CC + tid] = a3;

    if (tid < 4) {
        float s = 0.f;
        for (int e = 0; e < CC; e++)
            s += Wu[(size_t)(d0 + tid) * 512 + 256 + e] * bv[e];
        g_bvu[d0 + tid] = s;
    }
}

// ---------------- K0b: precompute M = scale*Wk^T Wq, qtb, wqbk, bqbk ----------
__global__ void __launch_bounds__(256) k_prep2(const float* __restrict__ Wq,
                                               const float* __restrict__ Wk,
                                               const float* __restrict__ bq,
                                               const float* __restrict__ bk) {
    __shared__ __align__(16) float sWq[32 * 260];
    __shared__ float wkc[32][4];
    int tid = threadIdx.x;

    if (blockIdx.x == 64) {
        float s = 0.f;
        #pragma unroll 8
        for (int d = 0; d < CC; d++) s += Wq[(size_t)d * CC + tid] * bk[d];
        g_wqbk[tid] = SCALE * s;
        float* red = sWq;
        float p = block_reduce_256(bq[tid] * bk[tid], red, tid);
        if (tid == 0) g_bqbk = SCALE * p;
        return;
    }

    int c0 = blockIdx.x * 4;
    float a0 = 0.f, a1 = 0.f, a2 = 0.f, a3 = 0.f;
    for (int ch = 0; ch < 8; ch++) {
        #pragma unroll
        for (int it = 0; it < 32; it++)
            sWq[it * 260 + tid] = Wq[(size_t)(ch * 32 + it) * CC + tid];
        if (tid < 128) {
            int dl = tid >> 2, cl = tid & 3;
            wkc[dl][cl] = Wk[(size_t)(ch * 32 + dl) * CC + c0 + cl];
        }
        __syncthreads();
        #pragma unroll
        for (int dl = 0; dl < 32; dl++) {
            float x = sWq[dl * 260 + tid];
            a0 += wkc[dl][0] * x; a1 += wkc[dl][1] * x;
            a2 += wkc[dl][2] * x; a3 += wkc[dl][3] * x;
        }
        __syncthreads();
    }
    g_Wqk[(size_t)(c0 + 0) * CC + tid] = SCALE * a0;
    g_Wqk[(size_t)(c0 + 1) * CC + tid] = SCALE * a1;
    g_Wqk[(size_t)(c0 + 2) * CC + tid] = SCALE * a2;
    g_Wqk[(size_t)(c0 + 3) * CC + tid] = SCALE * a3;

    if (tid < 4) {
        float s = 0.f;
        for (int d = 0; d < CC; d++) s += Wk[(size_t)d * CC + c0 + tid] * bq[d];
        g_qtb[c0 + tid] = SCALE * s;
    }
}

// ---------------- K1: LayerNorm of transposed input -> fp16 xnl (b,n,c) ----------
__global__ void __launch_bounds__(256) k_ln_input(const float* __restrict__ x,
                                                  const float* __restrict__ lg,
                                                  const float* __restrict__ lb) {
    __shared__ float sm[CC * 33];
    __shared__ float ps[8][32], pq[8][32];
    __shared__ float mu[32], rs[32];
    int b = blockIdx.x >> 7;
    int tile = blockIdx.x & 127;
    int n0 = tile * 32;
    int tid = threadIdx.x;

    const float* xb = x + ((size_t)b * CC) * HWN + n0;
    #pragma unroll
    for (int it = 0; it < 32; it++) {
        int idx = it * 256 + tid;
        int n = idx & 31, c = idx >> 5;
        sm[c * 33 + n] = xb[(size_t)c * HWN + n];
    }
    __syncthreads();

    int p = tid >> 5, tn = tid & 31;
    float s = 0.f, sq = 0.f;
    #pragma unroll
    for (int cc = 0; cc < 32; cc++) {
        float v = sm[(p * 32 + cc) * 33 + tn];
        s += v; sq += v * v;
    }
    ps[p][tn] = s; pq[p][tn] = sq;
    __syncthreads();
    if (tid < 32) {
        float S = 0.f, Q = 0.f;
        #pragma unroll
        for (int i = 0; i < 8; i++) { S += ps[i][tid]; Q += pq[i][tid]; }
        float m = S * (1.0f / 256.0f);
        float var = Q * (1.0f / 256.0f) - m * m;
        mu[tid] = m;
        rs[tid] = rsqrtf(var + LN_EPS);
    }
    __syncthreads();

    float gc = lg[tid], bc = lb[tid];
    __half* out = g_xnl + ((size_t)(b * HWN + n0)) * CC;
    #pragma unroll
    for (int it = 0; it < 32; it++) {
        float v = sm[tid * 33 + it];
        out[(size_t)it * CC + tid] = __float2half_rn((v - mu[it]) * rs[it] * gc + bc);
    }
}

// ---------------- K2: init slots ----------------
__global__ void k_init_slots(const float* __restrict__ smu,
                             const float* __restrict__ slsig,
                             const float* __restrict__ noise) {
    int i = blockIdx.x * 256 + threadIdx.x;
    int c = threadIdx.x;
    g_slots[i] = smu[c] + expf(slsig[c]) * noise[i];
}

// ---------------- K3a: qt = M@LN(slots) + qtb, qb; zero A/S. grid 32, block 256 ----
__global__ void __launch_bounds__(256) k_qt(const float* __restrict__ lg,
                                            const float* __restrict__ lb) {
    __shared__ __align__(16) float sM[8 * 260];
    __shared__ __align__(16) float sg[CC], sb[CC];
    __shared__ float mu[64], rs[64];
    int c0 = blockIdx.x * 8;
    int tid = threadIdx.x;
    int warp = tid >> 5, lane = tid & 31;

    #pragma unroll
    for (int it = 0; it < 8; it++) {
        int idx = it * 256 + tid;
        sM[(idx >> 8) * 260 + (idx & 255)] = g_Wqk[(size_t)c0 * CC + idx];
    }
    sg[tid] = lg[tid];
    sb[tid] = lb[tid];

    #pragma unroll
    for (int rr = 0; rr < 8; rr++) {
        int row = warp * 8 + rr;
        const float4* pr = (const float4*)(g_slots + row * CC) + lane * 2;
        float4 v0 = pr[0], v1 = pr[1];
        float s = v0.x + v0.y + v0.z + v0.w + v1.x + v1.y + v1.z + v1.w;
        float q = v0.x * v0.x + v0.y * v0.y + v0.z * v0.z + v0.w * v0.w
                + v1.x * v1.x + v1.y * v1.y + v1.z * v1.z + v1.w * v1.w;
        #pragma unroll
        for (int off = 16; off; off >>= 1) {
            s += __shfl_xor_sync(0xffffffffu, s, off);
            q += __shfl_xor_sync(0xffffffffu, q, off);
        }
        if (lane == 0) {
            float m = s * (1.0f / 256.0f);
            mu[row] = m;
            rs[row] = rsqrtf(q * (1.0f / 256.0f) - m * m + LN_EPS);
        }
    }

    g_A[blockIdx.x * 512 + tid] = 0.f;
    g_A[blockIdx.x * 512 + 256 + tid] = 0.f;
    if (blockIdx.x == 0 && tid < BB * KK) g_S[tid] = 0.f;
    __syncthreads();

    if (blockIdx.x == 0) {
        #pragma unroll
        for (int rr = 0; rr < 8; rr++) {
            int row = warp * 8 + rr;
            float m_ = mu[row], r_ = rs[row];
            const float4* pr = (const float4*)(g_slots + row * CC) + lane * 2;
            const float4* wq = (const float4*)g_wqbk + lane * 2;
            const float4* g4 = (const float4*)sg + lane * 2;
            const float4* b4 = (const float4*)sb + lane * 2;
            float acc = 0.f;
            #pragma unroll
            for (int h = 0; h < 2; h++) {
                float4 v = pr[h], w = wq[h], g = g4[h], bb = b4[h];
                acc += ((v.x - m_) * r_ * g.x + bb.x) * w.x
                     + ((v.y - m_) * r_ * g.y + bb.y) * w.y
                     + ((v.z - m_) * r_ * g.z + bb.z) * w.z
                     + ((v.w - m_) * r_ * g.w + bb.w) * w.w;
            }
            #pragma unroll
            for (int off = 16; off; off >>= 1)
                acc += __shfl_xor_sync(0xffffffffu, acc, off);
            if (lane == 0) g_qb[row] = acc + g_bqbk;
        }
    }

    #pragma unroll
    for (int rep = 0; rep < 2; rep++) {
        int p = rep * 256 + tid;
        int row = p >> 3, cl = p & 7;
        float m_ = mu[row], r_ = rs[row];
        const float4* sp = (const float4*)(g_slots + row * CC);
        const float4* w4 = (const float4*)(sM + cl * 260);
        const float4* g4 = (const float4*)sg;
        const float4* b4 = (const float4*)sb;
        float acc = g_qtb[c0 + cl];
        #pragma unroll 8
        for (int i = 0; i < 64; i++) {
            float4 v = sp[i], w = w4[i], g = g4[i], bb = b4[i];
            acc += ((v.x - m_) * r_ * g.x + bb.x) * w.x
                 + ((v.y - m_) * r_ * g.y + bb.y) * w.y
                 + ((v.z - m_) * r_ * g.z + bb.z) * w.z
                 + ((v.w - m_) * r_ * g.w + bb.w) * w.w;
        }
        g_qt[row * CC + c0 + cl] = acc;
    }
}

// ---------------- K3b: smem-staged attention, no cross-lane reductions -----------
// grid 512 (b*32+tile of 128 tokens), block 256, dynamic smem SMEM_ATTN
__global__ void __launch_bounds__(256) k_attn() {
    extern __shared__ __align__(16) char smem_raw[];
    unsigned int* sx = (unsigned int*)(smem_raw + OFF_SX);   // [128][133] half2 words
    float2*   sqt  = (float2*)(smem_raw + OFF_QT);           // [4][128]
    float*    spart= (float*) (smem_raw + OFF_PART);         // [256][4]
    float*    sa   = (float*) (smem_raw + OFF_SA);           // [128][4]
    float*    sqb  = (float*) (smem_raw + OFF_QB);           // [4]
    float*    sred = (float*) (smem_raw + OFF_SRED);         // [4 warps][4]

    int b = blockIdx.x >> 5;
    int tile = blockIdx.x & 31;
    int tid = threadIdx.x;
    int n0 = tile * 128;

    // ---- phase 0: stage x tile (fp16) + qt + qb ----
    const uint4* gx = (const uint4*)(g_xnl + ((size_t)(b * HWN + n0)) * CC);
    #pragma unroll
    for (int it = 0; it < 16; it++) {
        int idx = it * 256 + tid;        // 0..4095
        int n = idx >> 5, c8 = idx & 31;
        uint4 u = gx[idx];
        unsigned int* dst = sx + n * 133 + c8 * 4;
        dst[0] = u.x; dst[1] = u.y; dst[2] = u.z; dst[3] = u.w;
    }
    #pragma unroll
    for (int it = 0; it < 2; it++) {
        int idx = it * 256 + tid;        // 0..511
        int k = idx >> 7, c2 = idx & 127;
        sqt[k * 128 + c2] = ((const float2*)(g_qt + (b * KK + k) * CC))[c2];
    }
    if (tid < 4) sqb[tid] = g_qb[b * KK + tid];
    __syncthreads();

    // ---- phase 1: logits, thread = (token, c-half), zero shuffles ----
    {
        int n = tid & 127, h = tid >> 7;
        const unsigned int* xrow = sx + n * 133 + h * 64;
        const float2* q0 = sqt + h * 64;
        const float2* q1 = sqt + 128 + h * 64;
        const float2* q2 = sqt + 256 + h * 64;
        const float2* q3 = sqt + 384 + h * 64;
        float p0 = 0.f, p1 = 0.f, p2 = 0.f, p3 = 0.f;
        #pragma unroll 8
        for (int i = 0; i < 64; i++) {
            __half2 hx = *(const __half2*)&xrow[i];
            float2 xf = __half22float2(hx);
            float2 a = q0[i]; p0 += xf.x * a.x + xf.y * a.y;
            float2 c = q1[i]; p1 += xf.x * c.x + xf.y * c.y;
            float2 d = q2[i]; p2 += xf.x * d.x + xf.y * d.y;
            float2 e = q3[i]; p3 += xf.x * e.x + xf.y * e.y;
        }
        ((float4*)spart)[tid] = make_float4(p0, p1, p2, p3);
    }
    __syncthreads();

    // ---- softmax per token (threads 0..127) + ssum warp-reduce ----
    if (tid < 128) {
        float4 pa = ((const float4*)spart)[tid];
        float4 pb = ((const float4*)spart)[tid + 128];
        float l0 = pa.x + pb.x + sqb[0];
        float l1 = pa.y + pb.y + sqb[1];
        float l2 = pa.z + pb.z + sqb[2];
        float l3 = pa.w + pb.w + sqb[3];
        float mx = fmaxf(fmaxf(l0, l1), fmaxf(l2, l3));
        float e0 = __expf(l0 - mx), e1 = __expf(l1 - mx);
        float e2 = __expf(l2 - mx), e3 = __expf(l3 - mx);
        float inv = __fdividef(1.0f, e0 + e1 + e2 + e3);
        float a0 = e0 * inv, a1 = e1 * inv, a2 = e2 * inv, a3 = e3 * inv;
        ((float4*)sa)[tid] = make_float4(a0, a1, a2, a3);
        float s0 = a0, s1 = a1, s2 = a2, s3 = a3;
        #pragma unroll
        for (int off = 16; off; off >>= 1) {
            s0 += __shfl_xor_sync(0xffffffffu, s0, off);
            s1 += __shfl_xor_sync(0xffffffffu, s1, off);
            s2 += __shfl_xor_sync(0xffffffffu, s2, off);
            s3 += __shfl_xor_sync(0xffffffffu, s3, off);
        }
        if ((tid & 31) == 0) {
            int w = tid >> 5;
            sred[w * 4 + 0] = s0; sred[w * 4 + 1] = s1;
            sred[w * 4 + 2] = s2; sred[w * 4 + 3] = s3;
        }
    }
    __syncthreads();
    if (tid < 4) {
        float s = sred[tid] + sred[4 + tid] + sred[8 + tid] + sred[12 + tid];
        atomicAdd(&g_S[b * KK + tid], s);
    }

    // ---- phase 2: accumulate A, warp = 32-channel slice ----
    {
        int w = tid >> 5, L = tid & 31;
        int word = w * 16 + (L & 15);
        bool hi = (L >= 16);
        float2 a0 = {0.f, 0.f}, a1 = {0.f, 0.f}, a2 = {0.f, 0.f}, a3 = {0.f, 0.f};
        #pragma unroll 8
        for (int t = 0; t < 64; t++) {
            // hi half offset by 16 tokens -> disjoint bank sets vs lo half
            int nn = hi ? (64 + ((t + 16) & 63)) : t;
            __half2 hx = *(const __half2*)&sx[nn * 133 + word];
            float2 xf = __half22float2(hx);
            float4 av = ((const float4*)sa)[nn];
            a0.x += av.x * xf.x; a0.y += av.x * xf.y;
            a1.x += av.y * xf.x; a1.y += av.y * xf.y;
            a2.x += av.z * xf.x; a2.y += av.z * xf.y;
            a3.x += av.w * xf.x; a3.y += av.w * xf.y;
        }
        a0.x += __shfl_down_sync(0xffffffffu, a0.x, 16);
        a0.y += __shfl_down_sync(0xffffffffu, a0.y, 16);
        a1.x += __shfl_down_sync(0xffffffffu, a1.x, 16);
        a1.y += __shfl_down_sync(0xffffffffu, a1.y, 16);
        a2.x += __shfl_down_sync(0xffffffffu, a2.x, 16);
        a2.y += __shfl_down_sync(0xffffffffu, a2.y, 16);
        a3.x += __shfl_down_sync(0xffffffffu, a3.x, 16);
        a3.y += __shfl_down_sync(0xffffffffu, a3.y, 16);
        if (!hi) {
            int c = 2 * word;
            float* A0 = g_A + (b * KK + 0) * CC + c;
            float* A1 = g_A + (b * KK + 1) * CC + c;
            float* A2 = g_A + (b * KK + 2) * CC + c;
            float* A3 = g_A + (b * KK + 3) * CC + c;
            atomicAdd(A0, a0.x); atomicAdd(A0 + 1, a0.y);
            atomicAdd(A1, a1.x); atomicAdd(A1 + 1, a1.y);
            atomicAdd(A2, a2.x); atomicAdd(A2 + 1, a2.y);
            atomicAdd(A3, a3.x); atomicAdd(A3 + 1, a3.y);
        }
    }
}

// ---------------- K3c: spre = prev@Wu1^T + (A/(S+e))@Wvu^T + b*bvu + bu + prev ------
__global__ void __launch_bounds__(256) k_spre2(const float* __restrict__ Wu,
                                               const float* __restrict__ bu) {
    __shared__ __align__(16) float sw1[8 * 260];
    __shared__ __align__(16) float swv[8 * 260];
    int d0 = blockIdx.x * 8;
    int tid = threadIdx.x;
    #pragma unroll
    for (int it = 0; it < 8; it++) {
        int idx = it * 256 + tid;
        int r = idx >> 8, c = idx & 255;
        sw1[r * 260 + c] = Wu[(size_t)(d0 + r) * 512 + c];
        swv[r * 260 + c] = g_Wvu[(size_t)(d0 + r) * CC + c];
    }
    __syncthreads();
    #pragma unroll
    for (int rep = 0; rep < 2; rep++) {
        int p = rep * 256 + tid;
        int row = p >> 3, dl = p & 7;
        int d = d0 + dl;
        float S = g_S[row];
        float inv = 1.0f / (S + EPS_W);
        float beta = S * inv;
        const float4* pr = (const float4*)(g_slots + row * CC);
        const float4* a4 = (const float4*)(g_A + row * CC);
        const float4* w1 = (const float4*)(sw1 + dl * 260);
        const float4* wv = (const float4*)(swv + dl * 260);
        float acc = bu[d] + g_slots[row * CC + d] + beta * g_bvu[d];
        float accA = 0.f;
        #pragma unroll 8
        for (int i = 0; i < 64; i++) {
            float4 a = pr[i], w = w1[i];
            acc += a.x * w.x + a.y * w.y + a.z * w.z + a.w * w.w;
            float4 u = a4[i], vv = wv[i];
            accA += u.x * vv.x + u.y * vv.y + u.z * vv.z + u.w * vv.w;
        }
        g_spre[row * CC + d] = acc + inv * accA;
    }
}

// ---------------- K3d: h = gelu(LN(spre) @ W1^T + b1), LN fused ----------------
__global__ void __launch_bounds__(256) k_hid(const float* __restrict__ W1,
                                             const float* __restrict__ b1,
                                             const float* __restrict__ lg,
                                             const float* __restrict__ lb) {
    __shared__ __align__(16) float sw[8 * 260];
    __shared__ __align__(16) float slg[CC], slb[CC];
    __shared__ float mu[64], rs[64];
    int j0 = blockIdx.x * 8;
    int tid = threadIdx.x;
    int warp = tid >> 5, lane = tid & 31;

    #pragma unroll
    for (int it = 0; it < 8; it++) {
        int idx = it * 256 + tid;
        sw[(idx >> 8) * 260 + (idx & 255)] = W1[(size_t)j0 * CC + idx];
    }
    slg[tid] = lg[tid];
    slb[tid] = lb[tid];

    #pragma unroll
    for (int rr = 0; rr < 8; rr++) {
        int row = warp * 8 + rr;
        const float4* pr = (const float4*)(g_spre + row * CC) + lane * 2;
        float4 v0 = pr[0], v1 = pr[1];
        float s = v0.x + v0.y + v0.z + v0.w + v1.x + v1.y + v1.z + v1.w;
        float q = v0.x * v0.x + v0.y * v0.y + v0.z * v0.z + v0.w * v0.w
                + v1.x * v1.x + v1.y * v1.y + v1.z * v1.z + v1.w * v1.w;
        #pragma unroll
        for (int off = 16; off; off >>= 1) {
            s += __shfl_xor_sync(0xffffffffu, s, off);
            q += __shfl_xor_sync(0xffffffffu, q, off);
        }
        if (lane == 0) {
            float m = s * (1.0f / 256.0f);
            mu[row] = m;
            rs[row] = rsqrtf(q * (1.0f / 256.0f) - m * m + LN_EPS);
        }
    }
    __syncthreads();

    #pragma unroll
    for (int rep = 0; rep < 2; rep++) {
        int p = rep * 256 + tid;
        int row = p >> 3, jl = p & 7;
        float m_ = mu[row], r_ = rs[row];
        const float4* sp = (const float4*)(g_spre + row * CC);
        const float4* w4 = (const float4*)(sw + jl * 260);
        const float4* g4 = (const float4*)slg;
        const float4* b4 = (const float4*)slb;
        float acc = b1[j0 + jl];
        #pragma unroll 8
        for (int i = 0; i < 64; i++) {
            float4 v = sp[i], w = w4[i], g = g4[i], bb = b4[i];
            acc += ((v.x - m_) * r_ * g.x + bb.x) * w.x
                 + ((v.y - m_) * r_ * g.y + bb.y) * w.y
                 + ((v.z - m_) * r_ * g.z + bb.z) * w.z
                 + ((v.w - m_) * r_ * g.w + bb.w) * w.w;
        }
        g_h[row * HIDN + j0 + jl] = gelu_f(acc);
    }
}

// ---------------- K3e: slots = spre + h @ W2^T + b2 ----------------
__global__ void __launch_bounds__(256) k_outp(const float* __restrict__ W2,
                                              const float* __restrict__ b2) {
    __shared__ __align__(16) float sw[8 * 516];
    int d0 = blockIdx.x * 8;
    int tid = threadIdx.x;
    #pragma unroll
    for (int it = 0; it < 16; it++) {
        int idx = it * 256 + tid;
        sw[(idx >> 9) * 516 + (idx & 511)] = W2[(size_t)d0 * HIDN + idx];
    }
    __syncthreads();
    #pragma unroll
    for (int rep = 0; rep < 2; rep++) {
        int p = rep * 256 + tid;
        int row = p >> 3, dl = p & 7;
        int d = d0 + dl;
        const float4* h4 = (const float4*)(g_h + row * HIDN);
        const float4* w4 = (const float4*)(sw + dl * 516);
        float acc = b2[d] + g_spre[row * CC + d];
        #pragma unroll 8
        for (int i = 0; i < 128; i++) {
            float4 a = h4[i], w = w4[i];
            acc += a.x * w.x + a.y * w.y + a.z * w.z + a.w * w.w;
        }
        g_slots[row * CC + d] = acc;
    }
}

// ---------------- K4: final head + output write ----------------
__global__ void __launch_bounds__(128) k_final(const float* __restrict__ We1,
                                               const float* __restrict__ be1,
                                               const float* __restrict__ We2,
                                               const float* __restrict__ be2,
                                               float* __restrict__ out) {
    __shared__ __align__(16) float s[CC];
    __shared__ float red[128];
    int row = blockIdx.x, tid = threadIdx.x;
    float v0 = g_slots[row * CC + tid];
    float v1 = g_slots[row * CC + tid + 128];
    s[tid] = v0; s[tid + 128] = v1;
    out[row * CC + tid] = v0;
    out[row * CC + tid + 128] = v1;
    __syncthreads();

    const float4* w4 = (const float4*)(We1 + (size_t)tid * CC);
    const float4* s4 = (const float4*)s;
    float acc = be1[tid];
    #pragma unroll 8
    for (int i = 0; i < 64; i++) {
        float4 a = s4[i], w = w4[i];
        acc += a.x * w.x + a.y * w.y + a.z * w.z + a.w * w.w;
    }
    float e = gelu_f(acc);
    red[tid] = e * We2[tid];
    __syncthreads();
    #pragma unroll
    for (int st = 64; st > 0; st >>= 1) {
        if (tid < st) red[tid] += red[tid + st];
        __syncthreads();
    }
    if (tid == 0) {
        float z = red[0] + be2[0];
        out[BB * KK * CC + row] = 1.0f / (1.0f + expf(-z));
    }
}

// ---------------- host ----------------
extern "C" void kernel_launch(void* const* d_in, const int* in_sizes, int n_in,
                              void* d_out, int out_size) {
    const float* x        = (const float*)d_in[0];
    const float* noise    = (const float*)d_in[1];
    const float* slot_mu  = (const float*)d_in[2];
    const float* slot_ls  = (const float*)d_in[3];
    const float* ln_in_g  = (const float*)d_in[4];
    const float* ln_in_b  = (const float*)d_in[5];
    const float* ln_sl_g  = (const float*)d_in[6];
    const float* ln_sl_b  = (const float*)d_in[7];
    const float* ln_mlp_g = (const float*)d_in[8];
    const float* ln_mlp_b = (const float*)d_in[9];
    const float* Wq = (const float*)d_in[10];
    const float* bq = (const float*)d_in[11];
    const float* Wk = (const float*)d_in[12];
    const float* bk = (const float*)d_in[13];
    const float* Wv = (const float*)d_in[14];
    const float* bv = (const float*)d_in[15];
    const float* Wu = (const float*)d_in[16];
    const float* bu = (const float*)d_in[17];
    const float* W1 = (const float*)d_in[18];
    const float* b1 = (const float*)d_in[19];
    const float* W2 = (const float*)d_in[20];
    const float* b2 = (const float*)d_in[21];
    const float* We1 = (const float*)d_in[22];
    const float* be1 = (const float*)d_in[23];
    const float* We2 = (const float*)d_in[24];
    const float* be2 = (const float*)d_in[25];
    float* out = (float*)d_out;

    static int attr_set = 0;
    if (!attr_set) {
        cudaFuncSetAttribute(k_attn, cudaFuncAttributeMaxDynamicSharedMemorySize,
                             SMEM_ATTN);
        attr_set = 1;
    }

    k_prep<<<64, 256>>>(Wu, Wv, bv);
    k_prep2<<<65, 256>>>(Wq, Wk, bq, bk);
    k_ln_input<<<2048, 256>>>(x, ln_in_g, ln_in_b);
    k_init_slots<<<64, 256>>>(slot_mu, slot_ls, noise);

    for (int it = 0; it < 3; it++) {
        k_qt<<<32, 256>>>(ln_sl_g, ln_sl_b);
        k_attn<<<512, 256, SMEM_ATTN>>>();
        k_spre2<<<32, 256>>>(Wu, bu);
        k_hid<<<64, 256>>>(W1, b1, ln_mlp_g, ln_mlp_b);
        k_outp<<<32, 256>>>(W2, b2);
    }

    k_final<<<64, 128>>>(We1, be1, We2, be2, out);
}

// round 7
// speedup vs baseline: 1.0914x; 1.0914x over previous
#include <cuda_runtime.h>
#include <cuda_fp16.h>
#include <cstdint>
#include <math.h>

#define BB   16
#define CC   256
#define HWN  4096
#define KK   4
#define HIDN 512
#define EPS_W 1e-8f
#define LN_EPS 1e-5f
#define SCALE 0.0625f   // C^-0.5 = 1/16

// ---------------- scratch (static device globals; no allocation) ----------------
static __device__ __align__(16) __half g_xnl [BB*HWN*CC];  // LN'd input (b,n,c) fp16
static __device__ __align__(16) float g_slots[BB*KK*CC];
static __device__ __align__(16) float g_qt  [BB*KK*CC];
static __device__            float g_qb  [BB*KK];
static __device__ __align__(16) float g_A   [BB*KK*CC];
static __device__            float g_S   [BB*KK];
// transposed weights (input-major) for coalesced row-local GEMVs
static __device__ __align__(16) float g_WuT [CC*CC];       // [c][d] = Wu1[d][c]
static __device__ __align__(16) float g_WvuT[CC*CC];       // [c][d] = (Wu2@Wv)[d][c]
static __device__ __align__(16) float g_W1T [CC*HIDN];     // [c][j] = W1[j][c]
static __device__ __align__(16) float g_W2T [HIDN*CC];     // [h][d] = W2[d][h]
static __device__ __align__(16) float g_WqkT[CC*CC];       // [e][c] = scale*(Wk^T Wq)[c][e]
static __device__ __align__(16) float g_We1T[CC*128];      // [c][j] = We1[j][c]
static __device__            float g_bvu [CC];             // Wu2 @ bv
static __device__            float g_qtb [CC];             // scale * Wk^T bq
static __device__ __align__(16) float g_wqbk[CC];          // scale * Wq^T bk
static __device__            float g_bqbk;

// dynamic smem layout for k_attn (bytes)
#define SX_WORDS   (128 * 133)
#define OFF_SX     0
#define OFF_QT     (SX_WORDS * 4)
#define OFF_PART   (OFF_QT + 4 * 128 * 8)
#define OFF_SA     (OFF_PART + 256 * 16)
#define OFF_QB     (OFF_SA + 128 * 16)
#define OFF_SRED   (OFF_QB + 16)
#define SMEM_ATTN  (OFF_SRED + 16 * 4 + 16)

__device__ __forceinline__ float gelu_f(float x) {
    return 0.5f * x * (1.0f + erff(x * 0.70710678118654752f));
}

__device__ __forceinline__ void fma4(float4& a, float s, const float4& w) {
    a.x += s * w.x; a.y += s * w.y; a.z += s * w.z; a.w += s * w.w;
}

__device__ __forceinline__ float block_reduce_256(float v, float* red, int tid) {
    red[tid] = v; __syncthreads();
    #pragma unroll
    for (int s = 128; s > 0; s >>= 1) {
        if (tid < s) red[tid] += red[tid + s];
        __syncthreads();
    }
    float r = red[0]; __syncthreads();
    return r;
}

// mean/rstd of a 256-float value (all 256 threads must call)
__device__ __forceinline__ float2 ln_stats(float v, float* red, int tid) {
    float s = block_reduce_256(v, red, tid);
    float m = s * (1.0f / 256.0f);
    float d = v - m;
    float q = block_reduce_256(d * d, red, tid);
    return make_float2(m, rsqrtf(q * (1.0f / 256.0f) + LN_EPS));
}

// ---------------- K0: ALL precompute in one kernel, grid 417 ----------------
__global__ void __launch_bounds__(256) k_prep_all(const float* __restrict__ Wq,
                                                  const float* __restrict__ Wk,
                                                  const float* __restrict__ bq,
                                                  const float* __restrict__ bk,
                                                  const float* __restrict__ Wv,
                                                  const float* __restrict__ bv,
                                                  const float* __restrict__ Wu,
                                                  const float* __restrict__ W1,
                                                  const float* __restrict__ W2,
                                                  const float* __restrict__ We1) {
    __shared__ __align__(16) float sbuf[32 * 260];
    __shared__ __align__(16) float wcs[CC * 4];     // FIX: was 32*4 (overflow in bid<64 branch)
    int bid = blockIdx.x;
    int tid = threadIdx.x;

    if (bid < 64) {
        // WvuT[c][d] = sum_e Wu[d][256+e] * Wv[e][c], rows d0..d0+3; bvu
        int d0 = bid * 4;
        for (int idx = tid; idx < CC * 4; idx += 256) {
            int dl = idx & 3, e = idx >> 2;
            wcs[e * 4 + dl] = Wu[(size_t)(d0 + dl) * 512 + 256 + e];
        }
        __syncthreads();
        float a0 = 0.f, a1 = 0.f, a2 = 0.f, a3 = 0.f;
        for (int ch = 0; ch < 8; ch++) {
            #pragma unroll
            for (int it = 0; it < 32; it++)
                sbuf[it * 260 + tid] = Wv[(size_t)(ch * 32 + it) * CC + tid];
            __syncthreads();
            #pragma unroll
            for (int el = 0; el < 32; el++) {
                float x = sbuf[el * 260 + tid];
                float4 w = *(const float4*)&wcs[(ch * 32 + el) * 4];
                a0 += w.x * x; a1 += w.y * x; a2 += w.z * x; a3 += w.w * x;
            }
            __syncthreads();
        }
        *(float4*)&g_WvuT[(size_t)tid * CC + d0] = make_float4(a0, a1, a2, a3);
        if (tid < 4) {
            float s = 0.f;
            for (int e = 0; e < CC; e++)
                s += Wu[(size_t)(d0 + tid) * 512 + 256 + e] * bv[e];
            g_bvu[d0 + tid] = s;
        }
    } else if (bid < 128) {
        // WqkT[e][c] = scale * sum_d Wk[d][c] * Wq[d][e], c0..c0+3; qtb
        int c0 = (bid - 64) * 4;
        float a0 = 0.f, a1 = 0.f, a2 = 0.f, a3 = 0.f;
        for (int ch = 0; ch < 8; ch++) {
            #pragma unroll
            for (int it = 0; it < 32; it++)
                sbuf[it * 260 + tid] = Wq[(size_t)(ch * 32 + it) * CC + tid];
            if (tid < 128) {
                int dl = tid >> 2, cl = tid & 3;
                wcs[dl * 4 + cl] = Wk[(size_t)(ch * 32 + dl) * CC + c0 + cl];
            }
            __syncthreads();
            #pragma unroll
            for (int dl = 0; dl < 32; dl++) {
                float x = sbuf[dl * 260 + tid];
                a0 += wcs[dl * 4 + 0] * x; a1 += wcs[dl * 4 + 1] * x;
                a2 += wcs[dl * 4 + 2] * x; a3 += wcs[dl * 4 + 3] * x;
            }
            __syncthreads();
        }
        *(float4*)&g_WqkT[(size_t)tid * CC + c0] =
            make_float4(SCALE * a0, SCALE * a1, SCALE * a2, SCALE * a3);
        if (tid < 4) {
            float s = 0.f;
            for (int d = 0; d < CC; d++) s += Wk[(size_t)d * CC + c0 + tid] * bq[d];
            g_qtb[c0 + tid] = SCALE * s;
        }
    } else if (bid == 128) {
        float s = 0.f;
        #pragma unroll 8
        for (int d = 0; d < CC; d++) s += Wq[(size_t)d * CC + tid] * bk[d];
        g_wqbk[tid] = SCALE * s;
        float p = block_reduce_256(bq[tid] * bk[tid], sbuf, tid);
        if (tid == 0) g_bqbk = SCALE * p;
    } else if (bid < 193) {
        int d0 = (bid - 129) * 4;
        float r0 = Wu[(size_t)(d0 + 0) * 512 + tid];
        float r1 = Wu[(size_t)(d0 + 1) * 512 + tid];
        float r2 = Wu[(size_t)(d0 + 2) * 512 + tid];
        float r3 = Wu[(size_t)(d0 + 3) * 512 + tid];
        *(float4*)&g_WuT[(size_t)tid * CC + d0] = make_float4(r0, r1, r2, r3);
    } else if (bid < 321) {
        int j0 = (bid - 193) * 4;
        float r0 = W1[(size_t)(j0 + 0) * CC + tid];
        float r1 = W1[(size_t)(j0 + 1) * CC + tid];
        float r2 = W1[(size_t)(j0 + 2) * CC + tid];
        float r3 = W1[(size_t)(j0 + 3) * CC + tid];
        *(float4*)&g_W1T[(size_t)tid * HIDN + j0] = make_float4(r0, r1, r2, r3);
    } else if (bid < 385) {
        int d0 = (bid - 321) * 4;
        #pragma unroll
        for (int hh = 0; hh < 2; hh++) {
            int h = hh * 256 + tid;
            float r0 = W2[(size_t)(d0 + 0) * HIDN + h];
            float r1 = W2[(size_t)(d0 + 1) * HIDN + h];
            float r2 = W2[(size_t)(d0 + 2) * HIDN + h];
            float r3 = W2[(size_t)(d0 + 3) * HIDN + h];
            *(float4*)&g_W2T[(size_t)h * CC + d0] = make_float4(r0, r1, r2, r3);
        }
    } else {
        int j0 = (bid - 385) * 4;   // j0 in [0,128)
        float r0 = We1[(size_t)(j0 + 0) * CC + tid];
        float r1 = We1[(size_t)(j0 + 1) * CC + tid];
        float r2 = We1[(size_t)(j0 + 2) * CC + tid];
        float r3 = We1[(size_t)(j0 + 3) * CC + tid];
        *(float4*)&g_We1T[(size_t)tid * 128 + j0] = make_float4(r0, r1, r2, r3);
    }
}

// ---------------- K1: LayerNorm of transposed input -> fp16 xnl (b,n,c) ----------
__global__ void __launch_bounds__(256) k_ln_input(const float* __restrict__ x,
                                                  const float* __restrict__ lg,
                                                  const float* __restrict__ lb) {
    __shared__ float sm[CC * 33];
    __shared__ float ps[8][32], pq[8][32];
    __shared__ float mu[32], rs[32];
    int b = blockIdx.x >> 7;
    int tile = blockIdx.x & 127;
    int n0 = tile * 32;
    int tid = threadIdx.x;

    const float* xb = x + ((size_t)b * CC) * HWN + n0;
    #pragma unroll
    for (int it = 0; it < 32; it++) {
        int idx = it * 256 + tid;
        int n = idx & 31, c = idx >> 5;
        sm[c * 33 + n] = xb[(size_t)c * HWN + n];
    }
    __syncthreads();

    int p = tid >> 5, tn = tid & 31;
    float s = 0.f, sq = 0.f;
    #pragma unroll
    for (int cc = 0; cc < 32; cc++) {
        float v = sm[(p * 32 + cc) * 33 + tn];
        s += v; sq += v * v;
    }
    ps[p][tn] = s; pq[p][tn] = sq;
    __syncthreads();
    if (tid < 32) {
        float S = 0.f, Q = 0.f;
        #pragma unroll
        for (int i = 0; i < 8; i++) { S += ps[i][tid]; Q += pq[i][tid]; }
        float m = S * (1.0f / 256.0f);
        float var = Q * (1.0f / 256.0f) - m * m;
        mu[tid] = m;
        rs[tid] = rsqrtf(var + LN_EPS);
    }
    __syncthreads();

    float gc = lg[tid], bc = lb[tid];
    __half* out = g_xnl + ((size_t)(b * HWN + n0)) * CC;
    #pragma unroll
    for (int it = 0; it < 32; it++) {
        float v = sm[tid * 33 + it];
        out[(size_t)it * CC + tid] = __float2half_rn((v - mu[it]) * rs[it] * gc + bc);
    }
}

// ---------------- K2: init slots + qt/qb for iter 1 + zero A/S. grid 64 ----------
__global__ void __launch_bounds__(256) k_init(const float* __restrict__ smu,
                                              const float* __restrict__ sls,
                                              const float* __restrict__ noise,
                                              const float* __restrict__ lsg,
                                              const float* __restrict__ lsb) {
    __shared__ float sLn[CC];
    __shared__ __align__(16) float spart[4][CC];
    __shared__ float red[CC];
    int tid = threadIdx.x;
    int row = blockIdx.x;

    float ns = smu[tid] + expf(sls[tid]) * noise[row * CC + tid];
    g_slots[row * CC + tid] = ns;
    float2 st = ln_stats(ns, red, tid);
    float lv = (ns - st.x) * st.y * lsg[tid] + lsb[tid];
    sLn[tid] = lv;
    __syncthreads();

    int og = tid & 63, cl = tid >> 6, c4 = og * 4;
    float4 acc = make_float4(0.f, 0.f, 0.f, 0.f);
    #pragma unroll 8
    for (int ci = 0; ci < 64; ci++) {
        int e = cl * 64 + ci;
        float4 w = *(const float4*)&g_WqkT[(size_t)e * CC + c4];
        fma4(acc, sLn[e], w);
    }
    *(float4*)&spart[cl][c4] = acc;
    __syncthreads();
    g_qt[row * CC + tid] = spart[0][tid] + spart[1][tid] + spart[2][tid]
                         + spart[3][tid] + g_qtb[tid];
    float p = block_reduce_256(lv * g_wqbk[tid], red, tid);
    if (tid == 0) { g_qb[row] = p + g_bqbk; g_S[row] = 0.f; }
    g_A[row * CC + tid] = 0.f;
}

// ---------------- K3: smem-staged attention (unchanged, passing) ----------------
__global__ void __launch_bounds__(256) k_attn() {
    extern __shared__ __align__(16) char smem_raw[];
    unsigned int* sx = (unsigned int*)(smem_raw + OFF_SX);
    float2*   sqt  = (float2*)(smem_raw + OFF_QT);
    float*    spart= (float*) (smem_raw + OFF_PART);
    float*    sa   = (float*) (smem_raw + OFF_SA);
    float*    sqb  = (float*) (smem_raw + OFF_QB);
    float*    sred = (float*) (smem_raw + OFF_SRED);

    int b = blockIdx.x >> 5;
    int tile = blockIdx.x & 31;
    int tid = threadIdx.x;
    int n0 = tile * 128;

    const uint4* gx = (const uint4*)(g_xnl + ((size_t)(b * HWN + n0)) * CC);
    #pragma unroll
    for (int it = 0; it < 16; it++) {
        int idx = it * 256 + tid;
        int n = idx >> 5, c8 = idx & 31;
        uint4 u = gx[idx];
        unsigned int* dst = sx + n * 133 + c8 * 4;
        dst[0] = u.x; dst[1] = u.y; dst[2] = u.z; dst[3] = u.w;
    }
    #pragma unroll
    for (int it = 0; it < 2; it++) {
        int idx = it * 256 + tid;
        int k = idx >> 7, c2 = idx & 127;
        sqt[k * 128 + c2] = ((const float2*)(g_qt + (b * KK + k) * CC))[c2];
    }
    if (tid < 4) sqb[tid] = g_qb[b * KK + tid];
    __syncthreads();

    {
        int n = tid & 127, h = tid >> 7;
        const unsigned int* xrow = sx + n * 133 + h * 64;
        const float2* q0 = sqt + h * 64;
        const float2* q1 = sqt + 128 + h * 64;
        const float2* q2 = sqt + 256 + h * 64;
        const float2* q3 = sqt + 384 + h * 64;
        float p0 = 0.f, p1 = 0.f, p2 = 0.f, p3 = 0.f;
        #pragma unroll 8
        for (int i = 0; i < 64; i++) {
            __half2 hx = *(const __half2*)&xrow[i];
            float2 xf = __half22float2(hx);
            float2 a = q0[i]; p0 += xf.x * a.x + xf.y * a.y;
            float2 c = q1[i]; p1 += xf.x * c.x + xf.y * c.y;
            float2 d = q2[i]; p2 += xf.x * d.x + xf.y * d.y;
            float2 e = q3[i]; p3 += xf.x * e.x + xf.y * e.y;
        }
        ((float4*)spart)[tid] = make_float4(p0, p1, p2, p3);
    }
    __syncthreads();

    if (tid < 128) {
        float4 pa = ((const float4*)spart)[tid];
        float4 pb = ((const float4*)spart)[tid + 128];
        float l0 = pa.x + pb.x + sqb[0];
        float l1 = pa.y + pb.y + sqb[1];
        float l2 = pa.z + pb.z + sqb[2];
        float l3 = pa.w + pb.w + sqb[3];
        float mx = fmaxf(fmaxf(l0, l1), fmaxf(l2, l3));
        float e0 = __expf(l0 - mx), e1 = __expf(l1 - mx);
        float e2 = __expf(l2 - mx), e3 = __expf(l3 - mx);
        float inv = __fdividef(1.0f, e0 + e1 + e2 + e3);
        float a0 = e0 * inv, a1 = e1 * inv, a2 = e2 * inv, a3 = e3 * inv;
        ((float4*)sa)[tid] = make_float4(a0, a1, a2, a3);
        float s0 = a0, s1 = a1, s2 = a2, s3 = a3;
        #pragma unroll
        for (int off = 16; off; off >>= 1) {
            s0 += __shfl_xor_sync(0xffffffffu, s0, off);
            s1 += __shfl_xor_sync(0xffffffffu, s1, off);
            s2 += __shfl_xor_sync(0xffffffffu, s2, off);
            s3 += __shfl_xor_sync(0xffffffffu, s3, off);
        }
        if ((tid & 31) == 0) {
            int w = tid >> 5;
            sred[w * 4 + 0] = s0; sred[w * 4 + 1] = s1;
            sred[w * 4 + 2] = s2; sred[w * 4 + 3] = s3;
        }
    }
    __syncthreads();
    if (tid < 4) {
        float s = sred[tid] + sred[4 + tid] + sred[8 + tid] + sred[12 + tid];
        atomicAdd(&g_S[b * KK + tid], s);
    }

    {
        int w = tid >> 5, L = tid & 31;
        int word = w * 16 + (L & 15);
        bool hi = (L >= 16);
        float2 a0 = {0.f, 0.f}, a1 = {0.f, 0.f}, a2 = {0.f, 0.f}, a3 = {0.f, 0.f};
        #pragma unroll 8
        for (int t = 0; t < 64; t++) {
            int nn = hi ? (64 + ((t + 16) & 63)) : t;
            __half2 hx = *(const __half2*)&sx[nn * 133 + word];
            float2 xf = __half22float2(hx);
            float4 av = ((const float4*)sa)[nn];
            a0.x += av.x * xf.x; a0.y += av.x * xf.y;
            a1.x += av.y * xf.x; a1.y += av.y * xf.y;
            a2.x += av.z * xf.x; a2.y += av.z * xf.y;
            a3.x += av.w * xf.x; a3.y += av.w * xf.y;
        }
        a0.x += __shfl_down_sync(0xffffffffu, a0.x, 16);
        a0.y += __shfl_down_sync(0xffffffffu, a0.y, 16);
        a1.x += __shfl_down_sync(0xffffffffu, a1.x, 16);
        a1.y += __shfl_down_sync(0xffffffffu, a1.y, 16);
        a2.x += __shfl_down_sync(0xffffffffu, a2.x, 16);
        a2.y += __shfl_down_sync(0xffffffffu, a2.y, 16);
        a3.x += __shfl_down_sync(0xffffffffu, a3.x, 16);
        a3.y += __shfl_down_sync(0xffffffffu, a3.y, 16);
        if (!hi) {
            int c = 2 * word;
            float* A0 = g_A + (b * KK + 0) * CC + c;
            float* A1 = g_A + (b * KK + 1) * CC + c;
            float* A2 = g_A + (b * KK + 2) * CC + c;
            float* A3 = g_A + (b * KK + 3) * CC + c;
            atomicAdd(A0, a0.x); atomicAdd(A0 + 1, a0.y);
            atomicAdd(A1, a1.x); atomicAdd(A1 + 1, a1.y);
            atomicAdd(A2, a2.x); atomicAdd(A2 + 1, a2.y);
            atomicAdd(A3, a3.x); atomicAdd(A3 + 1, a3.y);
        }
    }
}

// ---------------- K4: fused slot update (2 rows per block, grid 32) --------------
__global__ void __launch_bounds__(256) k_update(const float* __restrict__ bu,
                                                const float* __restrict__ b1,
                                                const float* __restrict__ b2,
                                                const float* __restrict__ lmg,
                                                const float* __restrict__ lmb,
                                                const float* __restrict__ lsg,
                                                const float* __restrict__ lsb,
                                                const float* __restrict__ be1,
                                                const float* __restrict__ We2,
                                                const float* __restrict__ be2,
                                                float* __restrict__ out,
                                                int last) {
    __shared__ float sIn0[CC], sIn1[CC];
    __shared__ float sA0[CC], sA1[CC];
    __shared__ float sSp0[CC], sSp1[CC];
    __shared__ float sH0[HIDN], sH1[HIDN];
    __shared__ __align__(16) float spart[4][512];
    __shared__ float red[CC];

    int tid = threadIdx.x;
    int r0 = blockIdx.x * 2, r1 = r0 + 1;
    int og = tid & 63, cl = tid >> 6;
    int d4 = og * 4;

    float S0 = g_S[r0], S1 = g_S[r1];
    float inv0 = 1.0f / (S0 + EPS_W), inv1 = 1.0f / (S1 + EPS_W);
    float beta0 = S0 * inv0, beta1 = S1 * inv1;
    sIn0[tid] = g_slots[r0 * CC + tid];
    sIn1[tid] = g_slots[r1 * CC + tid];
    sA0[tid] = g_A[r0 * CC + tid] * inv0;
    sA1[tid] = g_A[r1 * CC + tid] * inv1;
    __syncthreads();

    // ---- spre ----
    {
        float4 a0 = make_float4(0.f, 0.f, 0.f, 0.f), a1 = a0;
        #pragma unroll 8
        for (int ci = 0; ci < 64; ci++) {
            int c = cl * 64 + ci;
            float4 wu = *(const float4*)&g_WuT [(size_t)c * CC + d4];
            float4 wv = *(const float4*)&g_WvuT[(size_t)c * CC + d4];
            float x0 = sIn0[c], y0 = sA0[c];
            float x1 = sIn1[c], y1 = sA1[c];
            a0.x += x0 * wu.x + y0 * wv.x; a0.y += x0 * wu.y + y0 * wv.y;
            a0.z += x0 * wu.z + y0 * wv.z; a0.w += x0 * wu.w + y0 * wv.w;
            a1.x += x1 * wu.x + y1 * wv.x; a1.y += x1 * wu.y + y1 * wv.y;
            a1.z += x1 * wu.z + y1 * wv.z; a1.w += x1 * wu.w + y1 * wv.w;
        }
        *(float4*)&spart[cl][d4] = a0;
        *(float4*)&spart[cl][256 + d4] = a1;
    }
    __syncthreads();
    float bvu_d = g_bvu[tid], bu_d = bu[tid];
    float sp0 = spart[0][tid] + spart[1][tid] + spart[2][tid] + spart[3][tid]
              + bu_d + sIn0[tid] + beta0 * bvu_d;
    float sp1 = spart[0][256 + tid] + spart[1][256 + tid] + spart[2][256 + tid]
              + spart[3][256 + tid] + bu_d + sIn1[tid] + beta1 * bvu_d;
    sSp0[tid] = sp0; sSp1[tid] = sp1;
    __syncthreads();

    // ---- m = LN_mlp(spre) ----
    float2 st0 = ln_stats(sp0, red, tid);
    float2 st1 = ln_stats(sp1, red, tid);
    float lm_g = lmg[tid], lm_b = lmb[tid];
    sIn0[tid] = (sp0 - st0.x) * st0.y * lm_g + lm_b;
    sIn1[tid] = (sp1 - st1.x) * st1.y * lm_g + lm_b;
    __syncthreads();

    // ---- h = gelu(m @ W1^T + b1) ----
    #pragma unroll
    for (int p = 0; p < 2; p++) {
        float4 h0 = make_float4(0.f, 0.f, 0.f, 0.f), h1 = h0;
        int j4 = p * 256 + d4;
        #pragma unroll 8
        for (int ci = 0; ci < 64; ci++) {
            int c = cl * 64 + ci;
            float4 w = *(const float4*)&g_W1T[(size_t)c * HIDN + j4];
            fma4(h0, sIn0[c], w);
            fma4(h1, sIn1[c], w);
        }
        *(float4*)&spart[cl][d4] = h0;
        *(float4*)&spart[cl][256 + d4] = h1;
        __syncthreads();
        int j = p * 256 + tid;
        float b1j = b1[j];
        sH0[j] = gelu_f(spart[0][tid] + spart[1][tid] + spart[2][tid]
                        + spart[3][tid] + b1j);
        sH1[j] = gelu_f(spart[0][256 + tid] + spart[1][256 + tid]
                        + spart[2][256 + tid] + spart[3][256 + tid] + b1j);
        __syncthreads();
    }

    // ---- new slots = spre + h @ W2^T + b2 ----
    {
        float4 o0 = make_float4(0.f, 0.f, 0.f, 0.f), o1 = o0;
        #pragma unroll 8
        for (int ci = 0; ci < 128; ci++) {
            int c = cl * 128 + ci;
            float4 w = *(const float4*)&g_W2T[(size_t)c * CC + d4];
            fma4(o0, sH0[c], w);
            fma4(o1, sH1[c], w);
        }
        *(float4*)&spart[cl][d4] = o0;
        *(float4*)&spart[cl][256 + d4] = o1;
    }
    __syncthreads();
    float ns0 = spart[0][tid] + spart[1][tid] + spart[2][tid] + spart[3][tid]
              + b2[tid] + sSp0[tid];
    float ns1 = spart[0][256 + tid] + spart[1][256 + tid] + spart[2][256 + tid]
              + spart[3][256 + tid] + b2[tid] + sSp1[tid];
    g_slots[r0 * CC + tid] = ns0;
    g_slots[r1 * CC + tid] = ns1;
    sIn0[tid] = ns0; sIn1[tid] = ns1;
    __syncthreads();

    if (!last) {
        float2 t0 = ln_stats(ns0, red, tid);
        float2 t1 = ln_stats(ns1, red, tid);
        float ls_g = lsg[tid], ls_b = lsb[tid];
        float q0v = (ns0 - t0.x) * t0.y * ls_g + ls_b;
        float q1v = (ns1 - t1.x) * t1.y * ls_g + ls_b;
        sSp0[tid] = q0v; sSp1[tid] = q1v;
        __syncthreads();

        float4 a0 = make_float4(0.f, 0.f, 0.f, 0.f), a1 = a0;
        #pragma unroll 8
        for (int ci = 0; ci < 64; ci++) {
            int e = cl * 64 + ci;
            float4 w = *(const float4*)&g_WqkT[(size_t)e * CC + d4];
            fma4(a0, sSp0[e], w);
            fma4(a1, sSp1[e], w);
        }
        *(float4*)&spart[cl][d4] = a0;
        *(float4*)&spart[cl][256 + d4] = a1;
        __syncthreads();
        float qtb_c = g_qtb[tid];
        g_qt[r0 * CC + tid] = spart[0][tid] + spart[1][tid] + spart[2][tid]
                            + spart[3][tid] + qtb_c;
        g_qt[r1 * CC + tid] = spart[0][256 + tid] + spart[1][256 + tid]
                            + spart[2][256 + tid] + spart[3][256 + tid] + qtb_c;
        float w_ = g_wqbk[tid];
        float p0 = block_reduce_256(q0v * w_, red, tid);
        float p1 = block_reduce_256(q1v * w_, red, tid);
        if (tid == 0) {
            g_qb[r0] = p0 + g_bqbk;
            g_qb[r1] = p1 + g_bqbk;
            g_S[r0] = 0.f; g_S[r1] = 0.f;
        }
        g_A[r0 * CC + tid] = 0.f;
        g_A[r1 * CC + tid] = 0.f;
    } else {
        float2 e0 = make_float2(0.f, 0.f), e1 = e0;
        int j2 = og * 2;
        #pragma unroll 8
        for (int ci = 0; ci < 64; ci++) {
            int c = cl * 64 + ci;
            float2 w = *(const float2*)&g_We1T[(size_t)c * 128 + j2];
            float x0 = sIn0[c], x1 = sIn1[c];
            e0.x += x0 * w.x; e0.y += x0 * w.y;
            e1.x += x1 * w.x; e1.y += x1 * w.y;
        }
        spart[cl][j2] = e0.x; spart[cl][j2 + 1] = e0.y;
        spart[cl][256 + j2] = e1.x; spart[cl][256 + j2 + 1] = e1.y;
        __syncthreads();
        float pv;
        if (tid < 128) {
            float ee = gelu_f(spart[0][tid] + spart[1][tid] + spart[2][tid]
                              + spart[3][tid] + be1[tid]);
            pv = ee * We2[tid];
        } else {
            int j = tid - 128;
            float ee = gelu_f(spart[0][256 + j] + spart[1][256 + j]
                              + spart[2][256 + j] + spart[3][256 + j] + be1[j]);
            pv = ee * We2[j];
        }
        red[tid] = pv;
        __syncthreads();
        #pragma unroll
        for (int s = 64; s > 0; s >>= 1) {
            if ((tid & 127) < s) red[tid] += red[tid + s];
            __syncthreads();
        }
        if (tid == 0)   out[BB * KK * CC + r0] = 1.0f / (1.0f + expf(-(red[0]   + be2[0])));
        if (tid == 128) out[BB * KK * CC + r1] = 1.0f / (1.0f + expf(-(red[128] + be2[0])));
        out[r0 * CC + tid] = ns0;
        out[r1 * CC + tid] = ns1;
    }
}

// ---------------- host ----------------
extern "C" void kernel_launch(void* const* d_in, const int* in_sizes, int n_in,
                              void* d_out, int out_size) {
    const float* x        = (const float*)d_in[0];
    const float* noise    = (const float*)d_in[1];
    const float* slot_mu  = (const float*)d_in[2];
    const float* slot_ls  = (const float*)d_in[3];
    const float* ln_in_g  = (const float*)d_in[4];
    const float* ln_in_b  = (const float*)d_in[5];
    const float* ln_sl_g  = (const float*)d_in[6];
    const float* ln_sl_b  = (const float*)d_in[7];
    const float* ln_mlp_g = (const float*)d_in[8];
    const float* ln_mlp_b = (const float*)d_in[9];
    const float* Wq = (const float*)d_in[10];
    const float* bq = (const float*)d_in[11];
    const float* Wk = (const float*)d_in[12];
    const float* bk = (const float*)d_in[13];
    const float* Wv = (const float*)d_in[14];
    const float* bv = (const float*)d_in[15];
    const float* Wu = (const float*)d_in[16];
    const float* bu = (const float*)d_in[17];
    const float* W1 = (const float*)d_in[18];
    const float* b1 = (const float*)d_in[19];
    const float* W2 = (const float*)d_in[20];
    const float* b2 = (const float*)d_in[21];
    const float* We1 = (const float*)d_in[22];
    const float* be1 = (const float*)d_in[23];
    const float* We2 = (const float*)d_in[24];
    const float* be2 = (const float*)d_in[25];
    float* out = (float*)d_out;

    static int attr_set = 0;
    if (!attr_set) {
        cudaFuncSetAttribute(k_attn, cudaFuncAttributeMaxDynamicSharedMemorySize,
                             SMEM_ATTN);
        attr_set = 1;
    }

    k_prep_all<<<417, 256>>>(Wq, Wk, bq, bk, Wv, bv, Wu, W1, W2, We1);
    k_ln_input<<<2048, 256>>>(x, ln_in_g, ln_in_b);
    k_init<<<64, 256>>>(slot_mu, slot_ls, noise, ln_sl_g, ln_sl_b);

    for (int it = 0; it < 3; it++) {
        k_attn<<<512, 256, SMEM_ATTN>>>();
        k_update<<<32, 256>>>(bu, b1, b2, ln_mlp_g, ln_mlp_b, ln_sl_g, ln_sl_b,
                              be1, We2, be2, out, it == 2 ? 1 : 0);
    }
}

// round 8
// speedup vs baseline: 1.6568x; 1.5181x over previous
#include <cuda_runtime.h>
#include <cuda_fp16.h>
#include <cstdint>
#include <math.h>

#define BB   16
#define CC   256
#define HWN  4096
#define KK   4
#define HIDN 512
#define EPS_W 1e-8f
#define LN_EPS 1e-5f
#define SCALE 0.0625f   // C^-0.5 = 1/16
#define NBLK 256

// ---------------- scratch (static device globals; no allocation) ----------------
static __device__ __align__(16) __half g_xnl [BB*HWN*CC];  // LN'd input (b,n,c) fp16
static __device__ __align__(16) float g_slots[BB*KK*CC];
static __device__ __align__(16) float g_qt  [BB*KK*CC];
static __device__            float g_qb  [BB*KK];
static __device__ __align__(16) float g_A   [BB*KK*CC];
static __device__            float g_S   [BB*KK];
static __device__ __align__(16) float g_spre[BB*KK*CC];
static __device__ __align__(16) float g_h   [BB*KK*HIDN];
static __device__ __align__(16) float g_Wvu [CC*CC];   // (Wu2@Wv)[d][c] out-major
static __device__            float g_bvu [CC];         // Wu2 @ bv
static __device__ __align__(16) float g_Wqk [CC*CC];   // scale*(Wk^T Wq)[c_out][e] out-major
static __device__            float g_qtb [CC];         // scale * Wk^T bq
static __device__ __align__(16) float g_wqbk[CC];      // scale * Wq^T bk
static __device__            float g_bqbk;

// grid barrier state
static __device__ unsigned int g_bar_count = 0;
static __device__ volatile unsigned int g_bar_gen = 0;

// dynamic smem layout for attn phase (bytes)
#define SX_WORDS   (128 * 133)
#define OFF_SX     0
#define OFF_QT     (SX_WORDS * 4)
#define OFF_PART   (OFF_QT + 4 * 128 * 8)
#define OFF_SA     (OFF_PART + 256 * 16)
#define OFF_QB     (OFF_SA + 128 * 16)
#define OFF_SRED   (OFF_QB + 16)
#define SMEM_ATTN  (OFF_SRED + 16 * 4 + 16)   // ~78.4 KB

// update-phase layout (same dynamic smem, different view)
#define U_OFF_IN    0            // 4*512 floats max (8KB)
#define U_OFF_IN2   8192         // 4*256 floats (4KB)
#define U_OFF_SLAB  12288        // slabs up to ~33KB (x2 for S1)
#define U_OFF_RED   49152        // 256 floats scratch

__device__ __forceinline__ float gelu_f(float x) {
    return 0.5f * x * (1.0f + erff(x * 0.70710678118654752f));
}

__device__ __forceinline__ void grid_bar() {
    __syncthreads();
    if (threadIdx.x == 0) {
        __threadfence();                       // release: my block's writes -> L2
        unsigned int gen = g_bar_gen;
        if (atomicAdd(&g_bar_count, 1u) == NBLK - 1) {
            atomicExch(&g_bar_count, 0u);
            __threadfence();
            g_bar_gen = gen + 1;
        } else {
            while (g_bar_gen == gen) { __nanosleep(64); }
        }
        __threadfence();                       // acquire: invalidate L1 (CCTL.IVALL)
    }
    __syncthreads();
}

// LN of 4 rows (stride 256) held in smem `sin`, in place; red = 256-float scratch.
__device__ __forceinline__ void ln_apply4(float* sin, float* red,
                                          const float* __restrict__ gg,
                                          const float* __restrict__ bb, int tid) {
    int r = tid >> 6, t = tid & 63;
    float4 v = ((const float4*)(sin + r * 256))[t];
    float s = v.x + v.y + v.z + v.w;
    float q = v.x * v.x + v.y * v.y + v.z * v.z + v.w * v.w;
    #pragma unroll
    for (int off = 16; off; off >>= 1) {
        s += __shfl_xor_sync(0xffffffffu, s, off);
        q += __shfl_xor_sync(0xffffffffu, q, off);
    }
    int w = tid >> 5;
    if ((tid & 31) == 0) { red[w * 2] = s; red[w * 2 + 1] = q; }
    __syncthreads();
    if (tid < 4) {
        float S = red[tid * 4] + red[tid * 4 + 2];
        float Q = red[tid * 4 + 1] + red[tid * 4 + 3];
        float m = S * (1.0f / 256.0f);
        red[16 + tid * 2] = m;
        red[17 + tid * 2] = rsqrtf(Q * (1.0f / 256.0f) - m * m + LN_EPS);
    }
    __syncthreads();
    #pragma unroll
    for (int i = 0; i < 4; i++) {
        int idx = i * 256 + tid; int rr = idx >> 8, c = idx & 255;
        float m = red[16 + rr * 2], rstd = red[17 + rr * 2];
        sin[rr * 256 + c] = (sin[rr * 256 + c] - m) * rstd * gg[c] + bb[c];
    }
    __syncthreads();
}

// ---------------- prep: Wvu/Wqk out-major + bias folds, grid 129 ----------------
__global__ void __launch_bounds__(256) k_prep(const float* __restrict__ Wq,
                                              const float* __restrict__ Wk,
                                              const float* __restrict__ bq,
                                              const float* __restrict__ bk,
                                              const float* __restrict__ Wv,
                                              const float* __restrict__ bv,
                                              const float* __restrict__ Wu) {
    __shared__ __align__(16) float sbuf[32 * 260];
    __shared__ __align__(16) float wcs[CC * 4];
    int bid = blockIdx.x;
    int tid = threadIdx.x;

    if (bid < 64) {
        int d0 = bid * 4;
        for (int idx = tid; idx < CC * 4; idx += 256) {
            int dl = idx & 3, e = idx >> 2;
            wcs[e * 4 + dl] = Wu[(size_t)(d0 + dl) * 512 + 256 + e];
        }
        __syncthreads();
        float a0 = 0.f, a1 = 0.f, a2 = 0.f, a3 = 0.f;
        for (int ch = 0; ch < 8; ch++) {
            #pragma unroll
            for (int it = 0; it < 32; it++)
                sbuf[it * 260 + tid] = Wv[(size_t)(ch * 32 + it) * CC + tid];
            __syncthreads();
            #pragma unroll
            for (int el = 0; el < 32; el++) {
                float x = sbuf[el * 260 + tid];
                float4 w = *(const float4*)&wcs[(ch * 32 + el) * 4];
                a0 += w.x * x; a1 += w.y * x; a2 += w.z * x; a3 += w.w * x;
            }
            __syncthreads();
        }
        g_Wvu[(size_t)(d0 + 0) * CC + tid] = a0;
        g_Wvu[(size_t)(d0 + 1) * CC + tid] = a1;
        g_Wvu[(size_t)(d0 + 2) * CC + tid] = a2;
        g_Wvu[(size_t)(d0 + 3) * CC + tid] = a3;
        if (tid < 4) {
            float s = 0.f;
            for (int e = 0; e < CC; e++)
                s += Wu[(size_t)(d0 + tid) * 512 + 256 + e] * bv[e];
            g_bvu[d0 + tid] = s;
        }
    } else if (bid < 128) {
        int c0 = (bid - 64) * 4;
        float a0 = 0.f, a1 = 0.f, a2 = 0.f, a3 = 0.f;
        for (int ch = 0; ch < 8; ch++) {
            #pragma unroll
            for (int it = 0; it < 32; it++)
                sbuf[it * 260 + tid] = Wq[(size_t)(ch * 32 + it) * CC + tid];
            if (tid < 128) {
                int dl = tid >> 2, cl = tid & 3;
                wcs[dl * 4 + cl] = Wk[(size_t)(ch * 32 + dl) * CC + c0 + cl];
            }
            __syncthreads();
            #pragma unroll
            for (int dl = 0; dl < 32; dl++) {
                float x = sbuf[dl * 260 + tid];
                a0 += wcs[dl * 4 + 0] * x; a1 += wcs[dl * 4 + 1] * x;
                a2 += wcs[dl * 4 + 2] * x; a3 += wcs[dl * 4 + 3] * x;
            }
            __syncthreads();
        }
        g_Wqk[(size_t)(c0 + 0) * CC + tid] = SCALE * a0;
        g_Wqk[(size_t)(c0 + 1) * CC + tid] = SCALE * a1;
        g_Wqk[(size_t)(c0 + 2) * CC + tid] = SCALE * a2;
        g_Wqk[(size_t)(c0 + 3) * CC + tid] = SCALE * a3;
        if (tid < 4) {
            float s = 0.f;
            for (int d = 0; d < CC; d++) s += Wk[(size_t)d * CC + c0 + tid] * bq[d];
            g_qtb[c0 + tid] = SCALE * s;
        }
    } else {
        float s = 0.f;
        #pragma unroll 8
        for (int d = 0; d < CC; d++) s += Wq[(size_t)d * CC + tid] * bk[d];
        g_wqbk[tid] = SCALE * s;
        sbuf[tid] = bq[tid] * bk[tid];
        __syncthreads();
        #pragma unroll
        for (int st = 128; st > 0; st >>= 1) {
            if (tid < st) sbuf[tid] += sbuf[tid + st];
            __syncthreads();
        }
        if (tid == 0) g_bqbk = SCALE * sbuf[0];
    }
}

// ---------------- LN input kernel (unchanged) ----------------
__global__ void __launch_bounds__(256) k_ln_input(const float* __restrict__ x,
                                                  const float* __restrict__ lg,
                                                  const float* __restrict__ lb) {
    __shared__ float sm[CC * 33];
    __shared__ float ps[8][32], pq[8][32];
    __shared__ float mu[32], rs[32];
    int b = blockIdx.x >> 7;
    int tile = blockIdx.x & 127;
    int n0 = tile * 32;
    int tid = threadIdx.x;

    const float* xb = x + ((size_t)b * CC) * HWN + n0;
    #pragma unroll
    for (int it = 0; it < 32; it++) {
        int idx = it * 256 + tid;
        int n = idx & 31, c = idx >> 5;
        sm[c * 33 + n] = xb[(size_t)c * HWN + n];
    }
    __syncthreads();

    int p = tid >> 5, tn = tid & 31;
    float s = 0.f, sq = 0.f;
    #pragma unroll
    for (int cc = 0; cc < 32; cc++) {
        float v = sm[(p * 32 + cc) * 33 + tn];
        s += v; sq += v * v;
    }
    ps[p][tn] = s; pq[p][tn] = sq;
    __syncthreads();
    if (tid < 32) {
        float S = 0.f, Q = 0.f;
        #pragma unroll
        for (int i = 0; i < 8; i++) { S += ps[i][tid]; Q += pq[i][tid]; }
        float m = S * (1.0f / 256.0f);
        float var = Q * (1.0f / 256.0f) - m * m;
        mu[tid] = m;
        rs[tid] = rsqrtf(var + LN_EPS);
    }
    __syncthreads();

    float gc = lg[tid], bc = lb[tid];
    __half* out = g_xnl + ((size_t)(b * HWN + n0)) * CC;
    #pragma unroll
    for (int it = 0; it < 32; it++) {
        float v = sm[tid * 33 + it];
        out[(size_t)it * CC + tid] = __float2half_rn((v - mu[it]) * rs[it] * gc + bc);
    }
}

// ---------------- attn tile (device fn, dynamic smem) ----------------
__device__ __forceinline__ void attn_tile(int t, char* smraw, int tid) {
    unsigned int* sx = (unsigned int*)(smraw + OFF_SX);
    float2* sqt   = (float2*)(smraw + OFF_QT);
    float*  spart = (float*) (smraw + OFF_PART);
    float*  sa    = (float*) (smraw + OFF_SA);
    float*  sqb   = (float*) (smraw + OFF_QB);
    float*  sred  = (float*) (smraw + OFF_SRED);

    int b = t >> 5;
    int tile = t & 31;
    int n0 = tile * 128;

    const uint4* gx = (const uint4*)(g_xnl + ((size_t)(b * HWN + n0)) * CC);
    #pragma unroll
    for (int it = 0; it < 16; it++) {
        int idx = it * 256 + tid;
        int n = idx >> 5, c8 = idx & 31;
        uint4 u = gx[idx];
        unsigned int* dst = sx + n * 133 + c8 * 4;
        dst[0] = u.x; dst[1] = u.y; dst[2] = u.z; dst[3] = u.w;
    }
    #pragma unroll
    for (int it = 0; it < 2; it++) {
        int idx = it * 256 + tid;
        int k = idx >> 7, c2 = idx & 127;
        sqt[k * 128 + c2] = ((const float2*)(g_qt + (b * KK + k) * CC))[c2];
    }
    if (tid < 4) sqb[tid] = g_qb[b * KK + tid];
    __syncthreads();

    {
        int n = tid & 127, h = tid >> 7;
        const unsigned int* xrow = sx + n * 133 + h * 64;
        const float2* q0 = sqt + h * 64;
        const float2* q1 = sqt + 128 + h * 64;
        const float2* q2 = sqt + 256 + h * 64;
        const float2* q3 = sqt + 384 + h * 64;
        float p0 = 0.f, p1 = 0.f, p2 = 0.f, p3 = 0.f;
        #pragma unroll 8
        for (int i = 0; i < 64; i++) {
            __half2 hx = *(const __half2*)&xrow[i];
            float2 xf = __half22float2(hx);
            float2 a = q0[i]; p0 += xf.x * a.x + xf.y * a.y;
            float2 c = q1[i]; p1 += xf.x * c.x + xf.y * c.y;
            float2 d = q2[i]; p2 += xf.x * d.x + xf.y * d.y;
            float2 e = q3[i]; p3 += xf.x * e.x + xf.y * e.y;
        }
        ((float4*)spart)[tid] = make_float4(p0, p1, p2, p3);
    }
    __syncthreads();

    if (tid < 128) {
        float4 pa = ((const float4*)spart)[tid];
        float4 pb = ((const float4*)spart)[tid + 128];
        float l0 = pa.x + pb.x + sqb[0];
        float l1 = pa.y + pb.y + sqb[1];
        float l2 = pa.z + pb.z + sqb[2];
        float l3 = pa.w + pb.w + sqb[3];
        float mx = fmaxf(fmaxf(l0, l1), fmaxf(l2, l3));
        float e0 = __expf(l0 - mx), e1 = __expf(l1 - mx);
        float e2 = __expf(l2 - mx), e3 = __expf(l3 - mx);
        float inv = __fdividef(1.0f, e0 + e1 + e2 + e3);
        float a0 = e0 * inv, a1 = e1 * inv, a2 = e2 * inv, a3 = e3 * inv;
        ((float4*)sa)[tid] = make_float4(a0, a1, a2, a3);
        float s0 = a0, s1 = a1, s2 = a2, s3 = a3;
        #pragma unroll
        for (int off = 16; off; off >>= 1) {
            s0 += __shfl_xor_sync(0xffffffffu, s0, off);
            s1 += __shfl_xor_sync(0xffffffffu, s1, off);
            s2 += __shfl_xor_sync(0xffffffffu, s2, off);
            s3 += __shfl_xor_sync(0xffffffffu, s3, off);
        }
        if ((tid & 31) == 0) {
            int w = tid >> 5;
            sred[w * 4 + 0] = s0; sred[w * 4 + 1] = s1;
            sred[w * 4 + 2] = s2; sred[w * 4 + 3] = s3;
        }
    }
    __syncthreads();
    if (tid < 4) {
        float s = sred[tid] + sred[4 + tid] + sred[8 + tid] + sred[12 + tid];
        atomicAdd(&g_S[b * KK + tid], s);
    }

    {
        int w = tid >> 5, L = tid & 31;
        int word = w * 16 + (L & 15);
        bool hi = (L >= 16);
        float2 a0 = {0.f, 0.f}, a1 = {0.f, 0.f}, a2 = {0.f, 0.f}, a3 = {0.f, 0.f};
        #pragma unroll 8
        for (int t2 = 0; t2 < 64; t2++) {
            int nn = hi ? (64 + ((t2 + 16) & 63)) : t2;
            __half2 hx = *(const __half2*)&sx[nn * 133 + word];
            float2 xf = __half22float2(hx);
            float4 av = ((const float4*)sa)[nn];
            a0.x += av.x * xf.x; a0.y += av.x * xf.y;
            a1.x += av.y * xf.x; a1.y += av.y * xf.y;
            a2.x += av.z * xf.x; a2.y += av.z * xf.y;
            a3.x += av.w * xf.x; a3.y += av.w * xf.y;
        }
        a0.x += __shfl_down_sync(0xffffffffu, a0.x, 16);
        a0.y += __shfl_down_sync(0xffffffffu, a0.y, 16);
        a1.x += __shfl_down_sync(0xffffffffu, a1.x, 16);
        a1.y += __shfl_down_sync(0xffffffffu, a1.y, 16);
        a2.x += __shfl_down_sync(0xffffffffu, a2.x, 16);
        a2.y += __shfl_down_sync(0xffffffffu, a2.y, 16);
        a3.x += __shfl_down_sync(0xffffffffu, a3.x, 16);
        a3.y += __shfl_down_sync(0xffffffffu, a3.y, 16);
        if (!hi) {
            int c = 2 * word;
            float* A0 = g_A + (b * KK + 0) * CC + c;
            float* A1 = g_A + (b * KK + 1) * CC + c;
            float* A2 = g_A + (b * KK + 2) * CC + c;
            float* A3 = g_A + (b * KK + 3) * CC + c;
            atomicAdd(A0, a0.x); atomicAdd(A0 + 1, a0.y);
            atomicAdd(A1, a1.x); atomicAdd(A1 + 1, a1.y);
            atomicAdd(A2, a2.x); atomicAdd(A2 + 1, a2.y);
            atomicAdd(A3, a3.x); atomicAdd(A3 + 1, a3.y);
        }
    }
    __syncthreads();   // protect smem reuse by caller
}

// ---------------- qt stage (also used at init): 256 blocks ----------------
__device__ __forceinline__ void qt_stage(char* smraw, int bid, int tid,
                                         const float* lsg, const float* lsb,
                                         int zeroAS) {
    float* uin  = (float*)(smraw + U_OFF_IN);
    float* slab = (float*)(smraw + U_OFF_SLAB);
    float* red  = (float*)(smraw + U_OFF_RED);
    int rg = bid >> 4, os = bid & 15;

    #pragma unroll
    for (int i = 0; i < 4; i++) {
        int idx = i * 256 + tid; int r = idx >> 8, c = idx & 255;
        uin[r * 256 + c] = g_slots[(rg * 4 + r) * 256 + c];
    }
    #pragma unroll
    for (int i = 0; i < 16; i++) {
        int idx = i * 256 + tid; int j = idx >> 8, c = idx & 255;
        slab[j * 260 + c] = g_Wqk[(size_t)(os * 16 + j) * 256 + c];
    }
    __syncthreads();
    ln_apply4(uin, red, lsg, lsb, tid);

    if (os == 0) {   // qb for this rowgroup
        int r = tid >> 6, t = tid & 63;
        float4 v = ((const float4*)(uin + r * 256))[t];
        float4 w = ((const float4*)g_wqbk)[t];
        float s = v.x * w.x + v.y * w.y + v.z * w.z + v.w * w.w;
        #pragma unroll
        for (int off = 16; off; off >>= 1) s += __shfl_xor_sync(0xffffffffu, s, off);
        if ((tid & 31) == 0) red[(tid >> 5) * 2] = s;
        __syncthreads();
        if (tid < 4) g_qb[rg * 4 + tid] = red[tid * 4] + red[tid * 4 + 2] + g_bqbk;
    }

    int r = tid >> 6, j = (tid >> 2) & 15, cq = tid & 3;
    float acc = 0.f;
    #pragma unroll 8
    for (int ci = 0; ci < 64; ci++) {
        int c = cq + ci * 4;
        acc += uin[r * 256 + c] * slab[j * 260 + c];
    }
    acc += __shfl_xor_sync(0xffffffffu, acc, 1);
    acc += __shfl_xor_sync(0xffffffffu, acc, 2);
    if (cq == 0) {
        int cc = os * 16 + j, row = rg * 4 + r;
        g_qt[row * 256 + cc] = acc + g_qtb[cc];
    }
    if (zeroAS) {
        if (tid < 64) {
            int r2 = tid >> 4, j2 = tid & 15;
            g_A[(rg * 4 + r2) * 256 + os * 16 + j2] = 0.f;
        }
        if (os == 0 && tid < 4) g_S[rg * 4 + tid] = 0.f;
    }
}

// ---------------- MEGA kernel: init + qt + 3x(attn + update) ----------------
__global__ void __launch_bounds__(256, 2) k_mega(
    const float* __restrict__ smu,  const float* __restrict__ sls,
    const float* __restrict__ noise,
    const float* __restrict__ lsg,  const float* __restrict__ lsb,
    const float* __restrict__ lmg,  const float* __restrict__ lmb,
    const float* __restrict__ Wu,   const float* __restrict__ bu,
    const float* __restrict__ W1,   const float* __restrict__ b1,
    const float* __restrict__ W2,   const float* __restrict__ b2,
    const float* __restrict__ We1,  const float* __restrict__ be1,
    const float* __restrict__ We2,  const float* __restrict__ be2,
    float* __restrict__ out) {
    extern __shared__ __align__(16) char smraw[];
    float* uin  = (float*)(smraw + U_OFF_IN);
    float* uin2 = (float*)(smraw + U_OFF_IN2);
    float* slab = (float*)(smraw + U_OFF_SLAB);
    float* slab2 = slab + 16 * 260;
    float* red  = (float*)(smraw + U_OFF_RED);
    int bid = blockIdx.x;
    int tid = threadIdx.x;
    int rg = bid >> 4, os = bid & 15;

    // ---- init: blocks 0..63, one row each ----
    if (bid < 64) {
        int row = bid;
        float ns = smu[tid] + expf(sls[tid]) * noise[row * 256 + tid];
        g_slots[row * 256 + tid] = ns;
        g_A[row * 256 + tid] = 0.f;
        if (tid == 0) g_S[row] = 0.f;
    }
    grid_bar();
    qt_stage(smraw, bid, tid, lsg, lsb, 0);
    grid_bar();

    for (int it = 0; it < 3; it++) {
        int last = (it == 2);
        attn_tile(bid, smraw, tid);
        attn_tile(bid + 256, smraw, tid);
        grid_bar();

        // ---- S1: spre ----
        {
            #pragma unroll
            for (int i = 0; i < 4; i++) {
                int idx = i * 256 + tid; int r = idx >> 8, c = idx & 255;
                int row = rg * 4 + r;
                uin[r * 256 + c] = g_slots[row * 256 + c];
                float Sv = g_S[row];
                uin2[r * 256 + c] = g_A[row * 256 + c] * (1.0f / (Sv + EPS_W));
            }
            #pragma unroll
            for (int i = 0; i < 16; i++) {
                int idx = i * 256 + tid; int j = idx >> 8, c = idx & 255;
                slab [j * 260 + c] = Wu[(size_t)(os * 16 + j) * 512 + c];
                slab2[j * 260 + c] = g_Wvu[(size_t)(os * 16 + j) * 256 + c];
            }
            __syncthreads();
            int r = tid >> 6, j = (tid >> 2) & 15, cq = tid & 3;
            float acc = 0.f;
            #pragma unroll 8
            for (int ci = 0; ci < 64; ci++) {
                int c = cq + ci * 4;
                acc += uin[r * 256 + c] * slab[j * 260 + c]
                     + uin2[r * 256 + c] * slab2[j * 260 + c];
            }
            acc += __shfl_xor_sync(0xffffffffu, acc, 1);
            acc += __shfl_xor_sync(0xffffffffu, acc, 2);
            if (cq == 0) {
                int d = os * 16 + j, row = rg * 4 + r;
                float Sv = g_S[row];
                float beta = Sv / (Sv + EPS_W);
                g_spre[row * 256 + d] = acc + bu[d] + uin[r * 256 + d]
                                      + beta * g_bvu[d];
            }
        }
        grid_bar();

        // ---- S2: h = gelu(LN_mlp(spre) @ W1^T + b1) ----
        {
            #pragma unroll
            for (int i = 0; i < 4; i++) {
                int idx = i * 256 + tid; int r = idx >> 8, c = idx & 255;
                uin[r * 256 + c] = g_spre[(rg * 4 + r) * 256 + c];
            }
            #pragma unroll
            for (int i = 0; i < 32; i++) {
                int idx = i * 256 + tid; int j = idx >> 8, c = idx & 255;
                slab[j * 258 + c] = W1[(size_t)(os * 32 + j) * 256 + c];
            }
            __syncthreads();
            ln_apply4(uin, red, lmg, lmb, tid);
            int r = tid >> 6, j = (tid >> 1) & 31, ch = tid & 1;
            float acc = 0.f;
            #pragma unroll 8
            for (int ci = 0; ci < 128; ci++) {
                int c = ch + ci * 2;
                acc += uin[r * 256 + c] * slab[j * 258 + c];
            }
            acc += __shfl_xor_sync(0xffffffffu, acc, 1);
            if (ch == 0) {
                int jj = os * 32 + j, row = rg * 4 + r;
                g_h[row * 512 + jj] = gelu_f(acc + b1[jj]);
            }
        }
        grid_bar();

        // ---- S3: slots = spre + h @ W2^T + b2 ----
        {
            #pragma unroll
            for (int i = 0; i < 8; i++) {
                int idx = i * 256 + tid; int r = idx >> 9, c = idx & 511;
                uin[r * 512 + c] = g_h[(rg * 4 + r) * 512 + c];
            }
            #pragma unroll
            for (int i = 0; i < 32; i++) {
                int idx = i * 256 + tid; int j = idx >> 9, c = idx & 511;
                slab[j * 516 + c] = W2[(size_t)(os * 16 + j) * 512 + c];
            }
            __syncthreads();
            int r = tid >> 6, j = (tid >> 2) & 15, cq = tid & 3;
            float acc = 0.f;
            #pragma unroll 8
            for (int ci = 0; ci < 128; ci++) {
                int c = cq + ci * 4;
                acc += uin[r * 512 + c] * slab[j * 516 + c];
            }
            acc += __shfl_xor_sync(0xffffffffu, acc, 1);
            acc += __shfl_xor_sync(0xffffffffu, acc, 2);
            if (cq == 0) {
                int d = os * 16 + j, row = rg * 4 + r;
                float val = acc + b2[d] + g_spre[row * 256 + d];
                g_slots[row * 256 + d] = val;
                if (last) out[row * 256 + d] = val;
            }
        }
        grid_bar();

        if (!last) {
            qt_stage(smraw, bid, tid, lsg, lsb, 1);
            grid_bar();
        } else {
            // ---- head: e = gelu(We1 @ slots + be1) -> g_qt reuse ----
            #pragma unroll
            for (int i = 0; i < 4; i++) {
                int idx = i * 256 + tid; int r = idx >> 8, c = idx & 255;
                uin[r * 256 + c] = g_slots[(rg * 4 + r) * 256 + c];
            }
            #pragma unroll
            for (int i = 0; i < 8; i++) {
                int idx = i * 256 + tid; int j = idx >> 8, c = idx & 255;
                slab[j * 264 + c] = We1[(size_t)(os * 8 + j) * 256 + c];
            }
            __syncthreads();
            int r = tid >> 6, j = (tid >> 3) & 7, c8 = tid & 7;
            float acc = 0.f;
            #pragma unroll 8
            for (int ci = 0; ci < 32; ci++) {
                int c = c8 + ci * 8;
                acc += uin[r * 256 + c] * slab[j * 264 + c];
            }
            acc += __shfl_xor_sync(0xffffffffu, acc, 1);
            acc += __shfl_xor_sync(0xffffffffu, acc, 2);
            acc += __shfl_xor_sync(0xffffffffu, acc, 4);
            if (c8 == 0) {
                int jj = os * 8 + j, row = rg * 4 + r;
                g_qt[row * 256 + jj] = gelu_f(acc + be1[jj]);
            }
            grid_bar();
            if (bid == 0) {
                int row = tid >> 2, p = tid & 3;
                float a2 = 0.f;
                #pragma unroll 8
                for (int k2 = 0; k2 < 32; k2++) {
                    int j2 = p + k2 * 4;
                    a2 += g_qt[row * 256 + j2] * We2[j2];
                }
                a2 += __shfl_xor_sync(0xffffffffu, a2, 1);
                a2 += __shfl_xor_sync(0xffffffffu, a2, 2);
                if (p == 0)
                    out[BB * KK * CC + row] = 1.0f / (1.0f + expf(-(a2 + be2[0])));
            }
        }
    }
}

// ---------------- host ----------------
extern "C" void kernel_launch(void* const* d_in, const int* in_sizes, int n_in,
                              void* d_out, int out_size) {
    const float* x        = (const float*)d_in[0];
    const float* noise    = (const float*)d_in[1];
    const float* slot_mu  = (const float*)d_in[2];
    const float* slot_ls  = (const float*)d_in[3];
    const float* ln_in_g  = (const float*)d_in[4];
    const float* ln_in_b  = (const float*)d_in[5];
    const float* ln_sl_g  = (const float*)d_in[6];
    const float* ln_sl_b  = (const float*)d_in[7];
    const float* ln_mlp_g = (const float*)d_in[8];
    const float* ln_mlp_b = (const float*)d_in[9];
    const float* Wq = (const float*)d_in[10];
    const float* bq = (const float*)d_in[11];
    const float* Wk = (const float*)d_in[12];
    const float* bk = (const float*)d_in[13];
    const float* Wv = (const float*)d_in[14];
    const float* bv = (const float*)d_in[15];
    const float* Wu = (const float*)d_in[16];
    const float* bu = (const float*)d_in[17];
    const float* W1 = (const float*)d_in[18];
    const float* b1 = (const float*)d_in[19];
    const float* W2 = (const float*)d_in[20];
    const float* b2 = (const float*)d_in[21];
    const float* We1 = (const float*)d_in[22];
    const float* be1 = (const float*)d_in[23];
    const float* We2 = (const float*)d_in[24];
    const float* be2 = (const float*)d_in[25];
    float* out = (float*)d_out;

    static int attr_set = 0;
    if (!attr_set) {
        cudaFuncSetAttribute(k_mega, cudaFuncAttributeMaxDynamicSharedMemorySize,
                             SMEM_ATTN);
        attr_set = 1;
    }

    k_prep<<<129, 256>>>(Wq, Wk, bq, bk, Wv, bv, Wu);
    k_ln_input<<<2048, 256>>>(x, ln_in_g, ln_in_b);
    k_mega<<<NBLK, 256, SMEM_ATTN>>>(slot_mu, slot_ls, noise,
                                     ln_sl_g, ln_sl_b, ln_mlp_g, ln_mlp_b,
                                     Wu, bu, W1, b1, W2, b2,
                                     We1, be1, We2, be2, out);
}

// round 9
// speedup vs baseline: 1.7956x; 1.0838x over previous
#include <cuda_runtime.h>
#include <cuda_fp16.h>
#include <cstdint>
#include <math.h>

#define BB   16
#define CC   256
#define HWN  4096
#define KK   4
#define HIDN 512
#define EPS_W 1e-8f
#define LN_EPS 1e-5f
#define SCALE 0.0625f   // C^-0.5 = 1/16
#define NBLK 256

// ---------------- scratch (static device globals; no allocation) ----------------
static __device__ __align__(16) __half g_xnl [BB*HWN*CC];  // LN'd input (b,n,c) fp16
static __device__ __align__(16) float g_slots[BB*KK*CC];
static __device__ __align__(16) float g_qt  [BB*KK*CC];
static __device__            float g_qb  [BB*KK];
static __device__ __align__(16) float g_A   [BB*KK*CC];
static __device__            float g_S   [BB*KK];
static __device__ __align__(16) float g_spre[BB*KK*CC];
static __device__ __align__(16) float g_h   [BB*KK*HIDN];
static __device__ __align__(16) float g_Wvu [CC*CC];   // (Wu2@Wv)[d][c] out-major
static __device__            float g_bvu [CC];         // Wu2 @ bv
static __device__ __align__(16) float g_Wqk [CC*CC];   // scale*(Wk^T Wq)[c_out][e]
static __device__            float g_qtb [CC];         // scale * Wk^T bq
static __device__ __align__(16) float g_wqbk[CC];      // scale * Wq^T bk
static __device__            float g_bqbk;

// grid barrier state
static __device__ unsigned int g_bar_count = 0;
static __device__ volatile unsigned int g_bar_gen = 0;

// dynamic smem layout for attn phase (bytes)
#define SX_WORDS   (128 * 133)
#define OFF_SX     0
#define OFF_QT     (SX_WORDS * 4)
#define OFF_PART   (OFF_QT + 4 * 128 * 8)
#define OFF_SA     (OFF_PART + 256 * 16)
#define OFF_QB     (OFF_SA + 128 * 16)
#define OFF_SRED   (OFF_QB + 16)
#define SMEM_ATTN  (OFF_SRED + 16 * 4 + 16)   // ~78.4 KB

// update-phase layout (same dynamic smem, different view)
#define U_OFF_IN    0
#define U_OFF_IN2   8192
#define U_OFF_SLAB  12288
#define U_OFF_RED   49152

__device__ __forceinline__ float gelu_f(float x) {
    return 0.5f * x * (1.0f + erff(x * 0.70710678118654752f));
}

__device__ __forceinline__ void grid_bar() {
    __syncthreads();
    if (threadIdx.x == 0) {
        __threadfence();
        unsigned int gen = g_bar_gen;
        if (atomicAdd(&g_bar_count, 1u) == NBLK - 1) {
            atomicExch(&g_bar_count, 0u);
            __threadfence();
            g_bar_gen = gen + 1;
        } else {
            while (g_bar_gen == gen) { __nanosleep(64); }
        }
        __threadfence();
    }
    __syncthreads();
}

// LN of 4 rows (stride 256) in smem `sin`, in place; red = 256-float scratch.
__device__ __forceinline__ void ln_apply4(float* sin, float* red,
                                          const float* __restrict__ gg,
                                          const float* __restrict__ bb, int tid) {
    int r = tid >> 6, t = tid & 63;
    float4 v = ((const float4*)(sin + r * 256))[t];
    float s = v.x + v.y + v.z + v.w;
    float q = v.x * v.x + v.y * v.y + v.z * v.z + v.w * v.w;
    #pragma unroll
    for (int off = 16; off; off >>= 1) {
        s += __shfl_xor_sync(0xffffffffu, s, off);
        q += __shfl_xor_sync(0xffffffffu, q, off);
    }
    int w = tid >> 5;
    if ((tid & 31) == 0) { red[w * 2] = s; red[w * 2 + 1] = q; }
    __syncthreads();
    if (tid < 4) {
        float S = red[tid * 4] + red[tid * 4 + 2];
        float Q = red[tid * 4 + 1] + red[tid * 4 + 3];
        float m = S * (1.0f / 256.0f);
        red[16 + tid * 2] = m;
        red[17 + tid * 2] = rsqrtf(Q * (1.0f / 256.0f) - m * m + LN_EPS);
    }
    __syncthreads();
    #pragma unroll
    for (int i = 0; i < 4; i++) {
        int idx = i * 256 + tid; int rr = idx >> 8, c = idx & 255;
        float m = red[16 + rr * 2], rstd = red[17 + rr * 2];
        sin[rr * 256 + c] = (sin[rr * 256 + c] - m) * rstd * gg[c] + bb[c];
    }
    __syncthreads();
}

// ---------------- phase-0 device fns (dynamic smem) ----------------
// prep GEMM unit: bid<64 -> Wvu rows; 64<=bid<128 -> Wqk cols
__device__ void prep_unit(int bid, char* smraw, int tid,
                          const float* __restrict__ Wq, const float* __restrict__ Wk,
                          const float* __restrict__ bq, const float* __restrict__ Wv,
                          const float* __restrict__ bv, const float* __restrict__ Wu) {
    float* sbuf = (float*)smraw;               // 32*260
    float* wcs  = sbuf + 32 * 260;             // CC*4
    if (bid < 64) {
        int d0 = bid * 4;
        for (int idx = tid; idx < CC * 4; idx += 256) {
            int dl = idx & 3, e = idx >> 2;
            wcs[e * 4 + dl] = Wu[(size_t)(d0 + dl) * 512 + 256 + e];
        }
        __syncthreads();
        float a0 = 0.f, a1 = 0.f, a2 = 0.f, a3 = 0.f;
        for (int ch = 0; ch < 8; ch++) {
            #pragma unroll
            for (int it = 0; it < 32; it++)
                sbuf[it * 260 + tid] = Wv[(size_t)(ch * 32 + it) * CC + tid];
            __syncthreads();
            #pragma unroll
            for (int el = 0; el < 32; el++) {
                float x = sbuf[el * 260 + tid];
                float4 w = *(const float4*)&wcs[(ch * 32 + el) * 4];
                a0 += w.x * x; a1 += w.y * x; a2 += w.z * x; a3 += w.w * x;
            }
            __syncthreads();
        }
        g_Wvu[(size_t)(d0 + 0) * CC + tid] = a0;
        g_Wvu[(size_t)(d0 + 1) * CC + tid] = a1;
        g_Wvu[(size_t)(d0 + 2) * CC + tid] = a2;
        g_Wvu[(size_t)(d0 + 3) * CC + tid] = a3;
        if (tid < 4) {
            float s = 0.f;
            for (int e = 0; e < CC; e++)
                s += Wu[(size_t)(d0 + tid) * 512 + 256 + e] * bv[e];
            g_bvu[d0 + tid] = s;
        }
    } else {
        int c0 = (bid - 64) * 4;
        float a0 = 0.f, a1 = 0.f, a2 = 0.f, a3 = 0.f;
        for (int ch = 0; ch < 8; ch++) {
            #pragma unroll
            for (int it = 0; it < 32; it++)
                sbuf[it * 260 + tid] = Wq[(size_t)(ch * 32 + it) * CC + tid];
            if (tid < 128) {
                int dl = tid >> 2, cl = tid & 3;
                wcs[dl * 4 + cl] = Wk[(size_t)(ch * 32 + dl) * CC + c0 + cl];
            }
            __syncthreads();
            #pragma unroll
            for (int dl = 0; dl < 32; dl++) {
                float x = sbuf[dl * 260 + tid];
                a0 += wcs[dl * 4 + 0] * x; a1 += wcs[dl * 4 + 1] * x;
                a2 += wcs[dl * 4 + 2] * x; a3 += wcs[dl * 4 + 3] * x;
            }
            __syncthreads();
        }
        g_Wqk[(size_t)(c0 + 0) * CC + tid] = SCALE * a0;
        g_Wqk[(size_t)(c0 + 1) * CC + tid] = SCALE * a1;
        g_Wqk[(size_t)(c0 + 2) * CC + tid] = SCALE * a2;
        g_Wqk[(size_t)(c0 + 3) * CC + tid] = SCALE * a3;
        if (tid < 4) {
            float s = 0.f;
            for (int d = 0; d < CC; d++) s += Wk[(size_t)d * CC + c0 + tid] * bq[d];
            g_qtb[c0 + tid] = SCALE * s;
        }
    }
    __syncthreads();
}

__device__ void prep_bias(char* smraw, int tid,
                          const float* __restrict__ Wq, const float* __restrict__ bq,
                          const float* __restrict__ bk) {
    float* sbuf = (float*)smraw;
    float s = 0.f;
    #pragma unroll 8
    for (int d = 0; d < CC; d++) s += Wq[(size_t)d * CC + tid] * bk[d];
    g_wqbk[tid] = SCALE * s;
    sbuf[tid] = bq[tid] * bk[tid];
    __syncthreads();
    #pragma unroll
    for (int st = 128; st > 0; st >>= 1) {
        if (tid < st) sbuf[tid] += sbuf[tid + st];
        __syncthreads();
    }
    if (tid == 0) g_bqbk = SCALE * sbuf[0];
    __syncthreads();
}

// one LN-input tile (32 tokens): t in [0,2048)
__device__ void ln_tile(int t, char* smraw, int tid,
                        const float* __restrict__ x,
                        const float* __restrict__ lg,
                        const float* __restrict__ lb) {
    float* sm = (float*)smraw;        // 256*33
    float* ps = sm + 256 * 33;        // 8*32
    float* pq = ps + 256;             // 8*32
    float* mu = pq + 256;             // 32
    float* rs = mu + 32;              // 32
    int b = t >> 7;
    int tile = t & 127;
    int n0 = tile * 32;
    __syncthreads();   // protect smem reuse across tiles

    const float* xb = x + ((size_t)b * CC) * HWN + n0;
    #pragma unroll
    for (int it = 0; it < 32; it++) {
        int idx = it * 256 + tid;
        int n = idx & 31, c = idx >> 5;
        sm[c * 33 + n] = xb[(size_t)c * HWN + n];
    }
    __syncthreads();

    int p = tid >> 5, tn = tid & 31;
    float s = 0.f, sq = 0.f;
    #pragma unroll
    for (int cc = 0; cc < 32; cc++) {
        float v = sm[(p * 32 + cc) * 33 + tn];
        s += v; sq += v * v;
    }
    ps[p * 32 + tn] = s; pq[p * 32 + tn] = sq;
    __syncthreads();
    if (tid < 32) {
        float S = 0.f, Q = 0.f;
        #pragma unroll
        for (int i = 0; i < 8; i++) { S += ps[i * 32 + tid]; Q += pq[i * 32 + tid]; }
        float m = S * (1.0f / 256.0f);
        float var = Q * (1.0f / 256.0f) - m * m;
        mu[tid] = m;
        rs[tid] = rsqrtf(var + LN_EPS);
    }
    __syncthreads();

    float gc = lg[tid], bc = lb[tid];
    __half* out = g_xnl + ((size_t)(b * HWN + n0)) * CC;
    #pragma unroll
    for (int it = 0; it < 32; it++) {
        float v = sm[tid * 33 + it];
        out[(size_t)it * CC + tid] = __float2half_rn((v - mu[it]) * rs[it] * gc + bc);
    }
}

// ---------------- attn tile (qt packed slot-interleaved) ----------------
__device__ __forceinline__ void attn_tile(int t, char* smraw, int tid) {
    unsigned int* sx = (unsigned int*)(smraw + OFF_SX);
    float*  sqtf  = (float*) (smraw + OFF_QT);    // [c2][sub][k] -> 2 float4 per c2
    float*  spart = (float*) (smraw + OFF_PART);
    float*  sa    = (float*) (smraw + OFF_SA);
    float*  sqb   = (float*) (smraw + OFF_QB);
    float*  sred  = (float*) (smraw + OFF_SRED);

    int b = t >> 5;
    int tile = t & 31;
    int n0 = tile * 128;

    const uint4* gx = (const uint4*)(g_xnl + ((size_t)(b * HWN + n0)) * CC);
    #pragma unroll
    for (int it = 0; it < 16; it++) {
        int idx = it * 256 + tid;
        int n = idx >> 5, c8 = idx & 31;
        uint4 u = gx[idx];
        unsigned int* dst = sx + n * 133 + c8 * 4;
        dst[0] = u.x; dst[1] = u.y; dst[2] = u.z; dst[3] = u.w;
    }
    // qt packed: sqtf[c2*8 + sub*4 + k] = qt[k][2*c2+sub]
    #pragma unroll
    for (int it = 0; it < 4; it++) {
        int idx = it * 256 + tid;
        int k = idx & 3, sub = (idx >> 2) & 1, c2 = idx >> 3;
        sqtf[c2 * 8 + sub * 4 + k] = g_qt[(b * KK + k) * CC + c2 * 2 + sub];
    }
    if (tid < 4) sqb[tid] = g_qb[b * KK + tid];
    __syncthreads();

    // phase 1: logits, thread = (token, half); 3 smem accesses/iter
    {
        int n = tid & 127, h = tid >> 7;
        const unsigned int* xrow = sx + n * 133 + h * 64;
        const float4* q4 = (const float4*)sqtf + h * 128;
        float p0 = 0.f, p1 = 0.f, p2 = 0.f, p3 = 0.f;
        #pragma unroll 8
        for (int i = 0; i < 64; i++) {
            __half2 hx = *(const __half2*)&xrow[i];
            float2 xf = __half22float2(hx);
            float4 qa = q4[2 * i];       // slots at even channel
            float4 qb = q4[2 * i + 1];   // slots at odd channel
            p0 += xf.x * qa.x + xf.y * qb.x;
            p1 += xf.x * qa.y + xf.y * qb.y;
            p2 += xf.x * qa.z + xf.y * qb.z;
            p3 += xf.x * qa.w + xf.y * qb.w;
        }
        ((float4*)spart)[tid] = make_float4(p0, p1, p2, p3);
    }
    __syncthreads();

    if (tid < 128) {
        float4 pa = ((const float4*)spart)[tid];
        float4 pb = ((const float4*)spart)[tid + 128];
        float l0 = pa.x + pb.x + sqb[0];
        float l1 = pa.y + pb.y + sqb[1];
        float l2 = pa.z + pb.z + sqb[2];
        float l3 = pa.w + pb.w + sqb[3];
        float mx = fmaxf(fmaxf(l0, l1), fmaxf(l2, l3));
        float e0 = __expf(l0 - mx), e1 = __expf(l1 - mx);
        float e2 = __expf(l2 - mx), e3 = __expf(l3 - mx);
        float inv = __fdividef(1.0f, e0 + e1 + e2 + e3);
        float a0 = e0 * inv, a1 = e1 * inv, a2 = e2 * inv, a3 = e3 * inv;
        ((float4*)sa)[tid] = make_float4(a0, a1, a2, a3);
        float s0 = a0, s1 = a1, s2 = a2, s3 = a3;
        #pragma unroll
        for (int off = 16; off; off >>= 1) {
            s0 += __shfl_xor_sync(0xffffffffu, s0, off);
            s1 += __shfl_xor_sync(0xffffffffu, s1, off);
            s2 += __shfl_xor_sync(0xffffffffu, s2, off);
            s3 += __shfl_xor_sync(0xffffffffu, s3, off);
        }
        if ((tid & 31) == 0) {
            int w = tid >> 5;
            sred[w * 4 + 0] = s0; sred[w * 4 + 1] = s1;
            sred[w * 4 + 2] = s2; sred[w * 4 + 3] = s3;
        }
    }
    __syncthreads();
    if (tid < 4) {
        float s = sred[tid] + sred[4 + tid] + sred[8 + tid] + sred[12 + tid];
        atomicAdd(&g_S[b * KK + tid], s);
    }

    // phase 2: accumulate A
    {
        int w = tid >> 5, L = tid & 31;
        int word = w * 16 + (L & 15);
        bool hi = (L >= 16);
        float2 a0 = {0.f, 0.f}, a1 = {0.f, 0.f}, a2 = {0.f, 0.f}, a3 = {0.f, 0.f};
        #pragma unroll 8
        for (int t2 = 0; t2 < 64; t2++) {
            int nn = hi ? (64 + ((t2 + 16) & 63)) : t2;
            __half2 hx = *(const __half2*)&sx[nn * 133 + word];
            float2 xf = __half22float2(hx);
            float4 av = ((const float4*)sa)[nn];
            a0.x += av.x * xf.x; a0.y += av.x * xf.y;
            a1.x += av.y * xf.x; a1.y += av.y * xf.y;
            a2.x += av.z * xf.x; a2.y += av.z * xf.y;
            a3.x += av.w * xf.x; a3.y += av.w * xf.y;
        }
        a0.x += __shfl_down_sync(0xffffffffu, a0.x, 16);
        a0.y += __shfl_down_sync(0xffffffffu, a0.y, 16);
        a1.x += __shfl_down_sync(0xffffffffu, a1.x, 16);
        a1.y += __shfl_down_sync(0xffffffffu, a1.y, 16);
        a2.x += __shfl_down_sync(0xffffffffu, a2.x, 16);
        a2.y += __shfl_down_sync(0xffffffffu, a2.y, 16);
        a3.x += __shfl_down_sync(0xffffffffu, a3.x, 16);
        a3.y += __shfl_down_sync(0xffffffffu, a3.y, 16);
        if (!hi) {
            int c = 2 * word;
            float* A0 = g_A + (b * KK + 0) * CC + c;
            float* A1 = g_A + (b * KK + 1) * CC + c;
            float* A2 = g_A + (b * KK + 2) * CC + c;
            float* A3 = g_A + (b * KK + 3) * CC + c;
            atomicAdd(A0, a0.x); atomicAdd(A0 + 1, a0.y);
            atomicAdd(A1, a1.x); atomicAdd(A1 + 1, a1.y);
            atomicAdd(A2, a2.x); atomicAdd(A2 + 1, a2.y);
            atomicAdd(A3, a3.x); atomicAdd(A3 + 1, a3.y);
        }
    }
    __syncthreads();
}

// ---------------- qt stage: 256 blocks ----------------
__device__ __forceinline__ void qt_stage(char* smraw, int bid, int tid,
                                         const float* lsg, const float* lsb,
                                         int zeroAS) {
    float* uin  = (float*)(smraw + U_OFF_IN);
    float* slab = (float*)(smraw + U_OFF_SLAB);
    float* red  = (float*)(smraw + U_OFF_RED);
    int rg = bid >> 4, os = bid & 15;

    #pragma unroll
    for (int i = 0; i < 4; i++) {
        int idx = i * 256 + tid; int r = idx >> 8, c = idx & 255;
        uin[r * 256 + c] = g_slots[(rg * 4 + r) * 256 + c];
    }
    #pragma unroll
    for (int i = 0; i < 16; i++) {
        int idx = i * 256 + tid; int j = idx >> 8, c = idx & 255;
        slab[j * 260 + c] = g_Wqk[(size_t)(os * 16 + j) * 256 + c];
    }
    __syncthreads();
    ln_apply4(uin, red, lsg, lsb, tid);

    if (os == 0) {
        int r = tid >> 6, t = tid & 63;
        float4 v = ((const float4*)(uin + r * 256))[t];
        float4 w = ((const float4*)g_wqbk)[t];
        float s = v.x * w.x + v.y * w.y + v.z * w.z + v.w * w.w;
        #pragma unroll
        for (int off = 16; off; off >>= 1) s += __shfl_xor_sync(0xffffffffu, s, off);
        if ((tid & 31) == 0) red[(tid >> 5) * 2] = s;
        __syncthreads();
        if (tid < 4) g_qb[rg * 4 + tid] = red[tid * 4] + red[tid * 4 + 2] + g_bqbk;
    }

    int r = tid >> 6, j = (tid >> 2) & 15, cq = tid & 3;
    float acc = 0.f;
    #pragma unroll 8
    for (int ci = 0; ci < 64; ci++) {
        int c = cq + ci * 4;
        acc += uin[r * 256 + c] * slab[j * 260 + c];
    }
    acc += __shfl_xor_sync(0xffffffffu, acc, 1);
    acc += __shfl_xor_sync(0xffffffffu, acc, 2);
    if (cq == 0) {
        int cc = os * 16 + j, row = rg * 4 + r;
        g_qt[row * 256 + cc] = acc + g_qtb[cc];
    }
    if (zeroAS) {
        if (tid < 64) {
            int r2 = tid >> 4, j2 = tid & 15;
            g_A[(rg * 4 + r2) * 256 + os * 16 + j2] = 0.f;
        }
        if (os == 0 && tid < 4) g_S[rg * 4 + tid] = 0.f;
    }
}

// ---------------- THE kernel: prep + ln + init + qt + 3x(attn + update) ---------
__global__ void __launch_bounds__(256, 2) k_mega(
    const float* __restrict__ x,
    const float* __restrict__ lig,  const float* __restrict__ lib,
    const float* __restrict__ smu,  const float* __restrict__ sls,
    const float* __restrict__ noise,
    const float* __restrict__ lsg,  const float* __restrict__ lsb,
    const float* __restrict__ lmg,  const float* __restrict__ lmb,
    const float* __restrict__ Wq,   const float* __restrict__ bq,
    const float* __restrict__ Wk,   const float* __restrict__ bk,
    const float* __restrict__ Wv,   const float* __restrict__ bv,
    const float* __restrict__ Wu,   const float* __restrict__ bu,
    const float* __restrict__ W1,   const float* __restrict__ b1,
    const float* __restrict__ W2,   const float* __restrict__ b2,
    const float* __restrict__ We1,  const float* __restrict__ be1,
    const float* __restrict__ We2,  const float* __restrict__ be2,
    float* __restrict__ out) {
    extern __shared__ __align__(16) char smraw[];
    float* uin  = (float*)(smraw + U_OFF_IN);
    float* uin2 = (float*)(smraw + U_OFF_IN2);
    float* slab = (float*)(smraw + U_OFF_SLAB);
    float* slab2 = slab + 16 * 260;
    float* red  = (float*)(smraw + U_OFF_RED);
    int bid = blockIdx.x;
    int tid = threadIdx.x;
    int rg = bid >> 4, os = bid & 15;

    // ================= phase 0: prep GEMMs + bias + init + LN input =============
    if (bid < 128) {
        prep_unit(bid, smraw, tid, Wq, Wk, bq, Wv, bv, Wu);
    } else if (bid == 128) {
        prep_bias(smraw, tid, Wq, bq, bk);
    } else if (bid < 193) {
        int row = bid - 129;
        float ns = smu[tid] + expf(sls[tid]) * noise[row * 256 + tid];
        g_slots[row * 256 + tid] = ns;
        g_A[row * 256 + tid] = 0.f;
        if (tid == 0) g_S[row] = 0.f;
    }
    // ln tiles: blocks 0..128 -> 4 tiles (0..515); blocks 129..255 -> rest strided
    if (bid <= 128) {
        #pragma unroll
        for (int i = 0; i < 4; i++) ln_tile(bid * 4 + i, smraw, tid, x, lig, lib);
    } else {
        for (int t = 516 + (bid - 129); t < 2048; t += 127)
            ln_tile(t, smraw, tid, x, lig, lib);
    }
    grid_bar();
    qt_stage(smraw, bid, tid, lsg, lsb, 0);
    grid_bar();

    // ================= 3 iterations =================
    for (int it = 0; it < 3; it++) {
        int last = (it == 2);
        attn_tile(bid, smraw, tid);
        attn_tile(bid + 256, smraw, tid);
        grid_bar();

        // ---- S1: spre ----
        {
            #pragma unroll
            for (int i = 0; i < 4; i++) {
                int idx = i * 256 + tid; int r = idx >> 8, c = idx & 255;
                int row = rg * 4 + r;
                uin[r * 256 + c] = g_slots[row * 256 + c];
                float Sv = g_S[row];
                uin2[r * 256 + c] = g_A[row * 256 + c] * (1.0f / (Sv + EPS_W));
            }
            #pragma unroll
            for (int i = 0; i < 16; i++) {
                int idx = i * 256 + tid; int j = idx >> 8, c = idx & 255;
                slab [j * 260 + c] = Wu[(size_t)(os * 16 + j) * 512 + c];
                slab2[j * 260 + c] = g_Wvu[(size_t)(os * 16 + j) * 256 + c];
            }
            __syncthreads();
            int r = tid >> 6, j = (tid >> 2) & 15, cq = tid & 3;
            float acc = 0.f;
            #pragma unroll 8
            for (int ci = 0; ci < 64; ci++) {
                int c = cq + ci * 4;
                acc += uin[r * 256 + c] * slab[j * 260 + c]
                     + uin2[r * 256 + c] * slab2[j * 260 + c];
            }
            acc += __shfl_xor_sync(0xffffffffu, acc, 1);
            acc += __shfl_xor_sync(0xffffffffu, acc, 2);
            if (cq == 0) {
                int d = os * 16 + j, row = rg * 4 + r;
                float Sv = g_S[row];
                float beta = Sv / (Sv + EPS_W);
                g_spre[row * 256 + d] = acc + bu[d] + uin[r * 256 + d]
                                      + beta * g_bvu[d];
            }
        }
        grid_bar();

        // ---- S2: h = gelu(LN_mlp(spre) @ W1^T + b1) ----
        {
            #pragma unroll
            for (int i = 0; i < 4; i++) {
                int idx = i * 256 + tid; int r = idx >> 8, c = idx & 255;
                uin[r * 256 + c] = g_spre[(rg * 4 + r) * 256 + c];
            }
            #pragma unroll
            for (int i = 0; i < 32; i++) {
                int idx = i * 256 + tid; int j = idx >> 8, c = idx & 255;
                slab[j * 258 + c] = W1[(size_t)(os * 32 + j) * 256 + c];
            }
            __syncthreads();
            ln_apply4(uin, red, lmg, lmb, tid);
            int r = tid >> 6, j = (tid >> 1) & 31, ch = tid & 1;
            float acc = 0.f;
            #pragma unroll 8
            for (int ci = 0; ci < 128; ci++) {
                int c = ch + ci * 2;
                acc += uin[r * 256 + c] * slab[j * 258 + c];
            }
            acc += __shfl_xor_sync(0xffffffffu, acc, 1);
            if (ch == 0) {
                int jj = os * 32 + j, row = rg * 4 + r;
                g_h[row * 512 + jj] = gelu_f(acc + b1[jj]);
            }
        }
        grid_bar();

        // ---- S3: slots = spre + h @ W2^T + b2 ----
        {
            #pragma unroll
            for (int i = 0; i < 8; i++) {
                int idx = i * 256 + tid; int r = idx >> 9, c = idx & 511;
                uin[r * 512 + c] = g_h[(rg * 4 + r) * 512 + c];
            }
            #pragma unroll
            for (int i = 0; i < 32; i++) {
                int idx = i * 256 + tid; int j = idx >> 9, c = idx & 511;
                slab[j * 516 + c] = W2[(size_t)(os * 16 + j) * 512 + c];
            }
            __syncthreads();
            int r = tid >> 6, j = (tid >> 2) & 15, cq = tid & 3;
            float acc = 0.f;
            #pragma unroll 8
            for (int ci = 0; ci < 128; ci++) {
                int c = cq + ci * 4;
                acc += uin[r * 512 + c] * slab[j * 516 + c];
            }
            acc += __shfl_xor_sync(0xffffffffu, acc, 1);
            acc += __shfl_xor_sync(0xffffffffu, acc, 2);
            if (cq == 0) {
                int d = os * 16 + j, row = rg * 4 + r;
                float val = acc + b2[d] + g_spre[row * 256 + d];
                g_slots[row * 256 + d] = val;
                if (last) out[row * 256 + d] = val;
            }
        }
        grid_bar();

        if (!last) {
            qt_stage(smraw, bid, tid, lsg, lsb, 1);
            grid_bar();
        } else {
            // ---- head: e = gelu(We1 @ slots + be1) -> g_qt reuse ----
            #pragma unroll
            for (int i = 0; i < 4; i++) {
                int idx = i * 256 + tid; int r = idx >> 8, c = idx & 255;
                uin[r * 256 + c] = g_slots[(rg * 4 + r) * 256 + c];
            }
            #pragma unroll
            for (int i = 0; i < 8; i++) {
                int idx = i * 256 + tid; int j = idx >> 8, c = idx & 255;
                slab[j * 264 + c] = We1[(size_t)(os * 8 + j) * 256 + c];
            }
            __syncthreads();
            int r = tid >> 6, j = (tid >> 3) & 7, c8 = tid & 7;
            float acc = 0.f;
            #pragma unroll 8
            for (int ci = 0; ci < 32; ci++) {
                int c = c8 + ci * 8;
                acc += uin[r * 256 + c] * slab[j * 264 + c];
            }
            acc += __shfl_xor_sync(0xffffffffu, acc, 1);
            acc += __shfl_xor_sync(0xffffffffu, acc, 2);
            acc += __shfl_xor_sync(0xffffffffu, acc, 4);
            if (c8 == 0) {
                int jj = os * 8 + j, row = rg * 4 + r;
                g_qt[row * 256 + jj] = gelu_f(acc + be1[jj]);
            }
            grid_bar();
            if (bid == 0) {
                int row = tid >> 2, p = tid & 3;
                float a2 = 0.f;
                #pragma unroll 8
                for (int k2 = 0; k2 < 32; k2++) {
                    int j2 = p + k2 * 4;
                    a2 += g_qt[row * 256 + j2] * We2[j2];
                }
                a2 += __shfl_xor_sync(0xffffffffu, a2, 1);
                a2 += __shfl_xor_sync(0xffffffffu, a2, 2);
                if (p == 0)
                    out[BB * KK * CC + row] = 1.0f / (1.0f + expf(-(a2 + be2[0])));
            }
        }
    }
}

// ---------------- host ----------------
extern "C" void kernel_launch(void* const* d_in, const int* in_sizes, int n_in,
                              void* d_out, int out_size) {
    const float* x        = (const float*)d_in[0];
    const float* noise    = (const float*)d_in[1];
    const float* slot_mu  = (const float*)d_in[2];
    const float* slot_ls  = (const float*)d_in[3];
    const float* ln_in_g  = (const float*)d_in[4];
    const float* ln_in_b  = (const float*)d_in[5];
    const float* ln_sl_g  = (const float*)d_in[6];
    const float* ln_sl_b  = (const float*)d_in[7];
    const float* ln_mlp_g = (const float*)d_in[8];
    const float* ln_mlp_b = (const float*)d_in[9];
    const float* Wq = (const float*)d_in[10];
    const float* bq = (const float*)d_in[11];
    const float* Wk = (const float*)d_in[12];
    const float* bk = (const float*)d_in[13];
    const float* Wv = (const float*)d_in[14];
    const float* bv = (const float*)d_in[15];
    const float* Wu = (const float*)d_in[16];
    const float* bu = (const float*)d_in[17];
    const float* W1 = (const float*)d_in[18];
    const float* b1 = (const float*)d_in[19];
    const float* W2 = (const float*)d_in[20];
    const float* b2 = (const float*)d_in[21];
    const float* We1 = (const float*)d_in[22];
    const float* be1 = (const float*)d_in[23];
    const float* We2 = (const float*)d_in[24];
    const float* be2 = (const float*)d_in[25];
    float* out = (float*)d_out;

    static int attr_set = 0;
    if (!attr_set) {
        cudaFuncSetAttribute(k_mega, cudaFuncAttributeMaxDynamicSharedMemorySize,
                             SMEM_ATTN);
        attr_set = 1;
    }

    k_mega<<<NBLK, 256, SMEM_ATTN>>>(x, ln_in_g, ln_in_b,
                                     slot_mu, slot_ls, noise,
                                     ln_sl_g, ln_sl_b, ln_mlp_g, ln_mlp_b,
                                     Wq, bq, Wk, bk, Wv, bv, Wu, bu,
                                     W1, b1, W2, b2,
                                     We1, be1, We2, be2, out);
}